// round 1
// baseline (speedup 1.0000x reference)
#include <cuda_runtime.h>
#include <cuda_bf16.h>
#include <math.h>

// Problem constants
#define BB 4
#define TT 1024
#define VV 32000
#define DD 1024
#define LL 8
#define HH 16
#define HDIM 64
#define NROWS (BB * TT)          // 4096
#define FFD (4 * DD)             // 4096

// ---------------- scratch (device globals: allocation-free rule) ----------
__device__ float g_x[NROWS * DD];
__device__ float g_h[NROWS * DD];
__device__ float g_q[NROWS * DD];
__device__ float g_k[NROWS * DD];
__device__ float g_v[NROWS * DD];
__device__ float g_att[NROWS * DD];
__device__ float g_ff[NROWS * FFD];

// ---------------- embedding ----------------------------------------------
__global__ void embed_kernel(const int* __restrict__ idx,
                             const float* __restrict__ tok,
                             const float* __restrict__ pos,
                             float* __restrict__ x)
{
    int row = blockIdx.x;            // 0..4095
    int t = row % TT;
    int id = idx[row];
    int tid = threadIdx.x;           // 256 threads, float4 => 1024 floats
    const float4* tp = (const float4*)(tok + (size_t)id * DD);
    const float4* pp = (const float4*)(pos + (size_t)t * DD);
    float4 a = tp[tid], b = pp[tid];
    float4 o = make_float4(a.x + b.x, a.y + b.y, a.z + b.z, a.w + b.w);
    ((float4*)(x + (size_t)row * DD))[tid] = o;
}

// ---------------- layernorm (row = 1024) ----------------------------------
__global__ void ln_kernel(const float* __restrict__ x,
                          const float* __restrict__ g,
                          const float* __restrict__ b,
                          float* __restrict__ y)
{
    int row = blockIdx.x;
    int tid = threadIdx.x;           // 256
    const float4* xr = (const float4*)(x + (size_t)row * DD);
    float4 v = xr[tid];
    float s  = v.x + v.y + v.z + v.w;
    float sq = v.x * v.x + v.y * v.y + v.z * v.z + v.w * v.w;
#pragma unroll
    for (int o = 16; o > 0; o >>= 1) {
        s  += __shfl_xor_sync(0xffffffffu, s, o);
        sq += __shfl_xor_sync(0xffffffffu, sq, o);
    }
    __shared__ float ss[8], ssq[8];
    int wid = tid >> 5;
    if ((tid & 31) == 0) { ss[wid] = s; ssq[wid] = sq; }
    __syncthreads();
    float S = 0.f, SQ = 0.f;
#pragma unroll
    for (int i = 0; i < 8; i++) { S += ss[i]; SQ += ssq[i]; }
    float mean = S * (1.f / DD);
    float var  = SQ * (1.f / DD) - mean * mean;
    float inv  = rsqrtf(var + 1e-5f);
    float4 gv = ((const float4*)g)[tid];
    float4 bv = ((const float4*)b)[tid];
    float4 o;
    o.x = (v.x - mean) * inv * gv.x + bv.x;
    o.y = (v.y - mean) * inv * gv.y + bv.y;
    o.z = (v.z - mean) * inv * gv.z + bv.z;
    o.w = (v.w - mean) * inv * gv.w + bv.w;
    ((float4*)(y + (size_t)row * DD))[tid] = o;
}

// ---------------- SGEMM: C[M,N] = A[M,K] @ B[K,N] (+bias)(+gelu)(+resid) --
// 128x128 tile, BK=8, 256 threads, 8x8 per thread. All dims % 128 == 0.
#define GF_BIAS  1
#define GF_GELU  2
#define GF_RESID 4

__global__ __launch_bounds__(256) void sgemm_kernel(
    const float* __restrict__ A, const float* __restrict__ B,
    const float* __restrict__ bias, const float* __restrict__ resid,
    float* __restrict__ C, int M, int N, int K, int flags)
{
    __shared__ float As[8][128];
    __shared__ float Bs[8][128];

    int tid = threadIdx.x;
    int col0 = blockIdx.x * 128;
    int row0 = blockIdx.y * 128;

    int aRow = tid >> 1;             // 0..127
    int aCol = (tid & 1) * 4;        // 0 or 4
    int bRow = tid >> 5;             // 0..7
    int bCol = (tid & 31) * 4;       // 0..124

    const float* Aptr = A + (size_t)(row0 + aRow) * K + aCol;
    const float* Bptr = B + (size_t)bRow * N + col0 + bCol;

    int ty = tid >> 4, tx = tid & 15;
    float acc[8][8];
#pragma unroll
    for (int i = 0; i < 8; i++)
#pragma unroll
        for (int j = 0; j < 8; j++) acc[i][j] = 0.f;

    for (int k0 = 0; k0 < K; k0 += 8) {
        float4 av = *(const float4*)(Aptr + k0);
        As[aCol + 0][aRow] = av.x;
        As[aCol + 1][aRow] = av.y;
        As[aCol + 2][aRow] = av.z;
        As[aCol + 3][aRow] = av.w;
        *(float4*)&Bs[bRow][bCol] = *(const float4*)(Bptr + (size_t)k0 * N);
        __syncthreads();
#pragma unroll
        for (int kk = 0; kk < 8; kk++) {
            float a[8], bq[8];
            *(float4*)&a[0]  = *(const float4*)&As[kk][ty * 8];
            *(float4*)&a[4]  = *(const float4*)&As[kk][ty * 8 + 4];
            *(float4*)&bq[0] = *(const float4*)&Bs[kk][tx * 8];
            *(float4*)&bq[4] = *(const float4*)&Bs[kk][tx * 8 + 4];
#pragma unroll
            for (int i = 0; i < 8; i++)
#pragma unroll
                for (int j = 0; j < 8; j++)
                    acc[i][j] += a[i] * bq[j];
        }
        __syncthreads();
    }

#pragma unroll
    for (int i = 0; i < 8; i++) {
        int row = row0 + ty * 8 + i;
#pragma unroll
        for (int j = 0; j < 8; j++) {
            int col = col0 + tx * 8 + j;
            float val = acc[i][j];
            if (flags & GF_BIAS) val += bias[col];
            if (flags & GF_GELU) val = 0.5f * val * (1.f + erff(val * 0.70710678118654752f));
            if (flags & GF_RESID) val += resid[(size_t)row * N + col];
            C[(size_t)row * N + col] = val;
        }
    }
}

// ---------------- causal attention (per-head, flash-lite) ------------------
// grid: (T/128, B*H), block 128. One thread = one query row; q and o in regs.
__global__ __launch_bounds__(128, 1) void attn_kernel(
    const float* __restrict__ Q, const float* __restrict__ K,
    const float* __restrict__ V, float* __restrict__ O)
{
    __shared__ float Ks[64][68];     // pad 68 to stagger banks on store
    __shared__ float Vs[64][68];

    int bh = blockIdx.y;
    int b = bh >> 4;
    int h = bh & 15;
    int tid = threadIdx.x;
    int qt = blockIdx.x * 128 + tid;         // query index 0..1023

    size_t base = ((size_t)b * TT) * DD + (size_t)h * HDIM;
    const float* qp = Q + base + (size_t)qt * DD;

    float qreg[64];
#pragma unroll
    for (int i = 0; i < 16; i++)
        *(float4*)&qreg[i * 4] = *(const float4*)(qp + i * 4);

    float acc[64];
#pragma unroll
    for (int d = 0; d < 64; d++) acc[d] = 0.f;
    float m = -1e30f, l = 0.f;
    const float scale = 0.125f;              // 1/sqrt(64)

    int kend = blockIdx.x * 128 + 128;       // max keys this block needs
    for (int kt0 = 0; kt0 < kend; kt0 += 64) {
        int r  = tid >> 1;
        int c0 = (tid & 1) * 32;
        const float* kp = K + base + (size_t)(kt0 + r) * DD + c0;
        const float* vp = V + base + (size_t)(kt0 + r) * DD + c0;
#pragma unroll
        for (int i = 0; i < 8; i++) {
            *(float4*)&Ks[r][c0 + i * 4] = *(const float4*)(kp + i * 4);
            *(float4*)&Vs[r][c0 + i * 4] = *(const float4*)(vp + i * 4);
        }
        __syncthreads();

        int jmax = qt - kt0 + 1;
        if (jmax > 64) jmax = 64;
        for (int j = 0; j < jmax; j++) {
            float s = 0.f;
#pragma unroll
            for (int d = 0; d < 64; d++) s += qreg[d] * Ks[j][d];
            s *= scale;
            if (s <= m) {
                float p = __expf(s - m);
                l += p;
#pragma unroll
                for (int d = 0; d < 64; d++) acc[d] += p * Vs[j][d];
            } else {
                float corr = __expf(m - s);
                l = l * corr + 1.f;
#pragma unroll
                for (int d = 0; d < 64; d++) acc[d] = acc[d] * corr + Vs[j][d];
                m = s;
            }
        }
        __syncthreads();
    }

    float inv = 1.f / l;
    float* op = O + base + (size_t)qt * DD;
#pragma unroll
    for (int d = 0; d < 64; d++) op[d] = acc[d] * inv;
}

// ---------------- host orchestration --------------------------------------
extern "C" void kernel_launch(void* const* d_in, const int* in_sizes, int n_in,
                              void* d_out, int out_size)
{
    const int*   idx    = (const int*)  d_in[0];
    const float* tok    = (const float*)d_in[1];
    const float* pos    = (const float*)d_in[2];
    const float* ln1g   = (const float*)d_in[3];
    const float* ln1b   = (const float*)d_in[4];
    const float* Wq     = (const float*)d_in[5];
    const float* bq     = (const float*)d_in[6];
    const float* Wk     = (const float*)d_in[7];
    const float* bk     = (const float*)d_in[8];
    const float* Wv     = (const float*)d_in[9];
    const float* bv     = (const float*)d_in[10];
    const float* Wo     = (const float*)d_in[11];
    const float* bo     = (const float*)d_in[12];
    const float* ln2g   = (const float*)d_in[13];
    const float* ln2b   = (const float*)d_in[14];
    const float* W1     = (const float*)d_in[15];
    const float* b1     = (const float*)d_in[16];
    const float* W2     = (const float*)d_in[17];
    const float* b2     = (const float*)d_in[18];
    const float* lnfg   = (const float*)d_in[19];
    const float* lnfb   = (const float*)d_in[20];
    const float* headW  = (const float*)d_in[21];
    float* out = (float*)d_out;

    float *x, *h, *q, *k, *v, *att, *ff;
    cudaGetSymbolAddress((void**)&x,   g_x);
    cudaGetSymbolAddress((void**)&h,   g_h);
    cudaGetSymbolAddress((void**)&q,   g_q);
    cudaGetSymbolAddress((void**)&k,   g_k);
    cudaGetSymbolAddress((void**)&v,   g_v);
    cudaGetSymbolAddress((void**)&att, g_att);
    cudaGetSymbolAddress((void**)&ff,  g_ff);

    embed_kernel<<<NROWS, 256>>>(idx, tok, pos, x);

    dim3 gDxD(DD / 128, NROWS / 128);        // (8, 32)
    dim3 gDx4D(FFD / 128, NROWS / 128);      // (32, 32)
    dim3 gAttn(TT / 128, BB * HH);           // (8, 64)

    for (int l = 0; l < LL; l++) {
        const float* Wq_l = Wq + (size_t)l * DD * DD;
        const float* Wk_l = Wk + (size_t)l * DD * DD;
        const float* Wv_l = Wv + (size_t)l * DD * DD;
        const float* Wo_l = Wo + (size_t)l * DD * DD;
        const float* W1_l = W1 + (size_t)l * DD * FFD;
        const float* W2_l = W2 + (size_t)l * FFD * DD;

        ln_kernel<<<NROWS, 256>>>(x, ln1g + l * DD, ln1b + l * DD, h);
        sgemm_kernel<<<gDxD, 256>>>(h, Wq_l, bq + l * DD, nullptr, q,
                                    NROWS, DD, DD, GF_BIAS);
        sgemm_kernel<<<gDxD, 256>>>(h, Wk_l, bk + l * DD, nullptr, k,
                                    NROWS, DD, DD, GF_BIAS);
        sgemm_kernel<<<gDxD, 256>>>(h, Wv_l, bv + l * DD, nullptr, v,
                                    NROWS, DD, DD, GF_BIAS);
        attn_kernel<<<gAttn, 128>>>(q, k, v, att);
        sgemm_kernel<<<gDxD, 256>>>(att, Wo_l, bo + l * DD, x, x,
                                    NROWS, DD, DD, GF_BIAS | GF_RESID);
        ln_kernel<<<NROWS, 256>>>(x, ln2g + l * DD, ln2b + l * DD, h);
        sgemm_kernel<<<gDx4D, 256>>>(h, W1_l, b1 + (size_t)l * FFD, nullptr, ff,
                                     NROWS, FFD, DD, GF_BIAS | GF_GELU);
        sgemm_kernel<<<gDxD, 256>>>(ff, W2_l, b2 + l * DD, x, x,
                                    NROWS, DD, FFD, GF_BIAS | GF_RESID);
    }

    ln_kernel<<<NROWS, 256>>>(x, lnfg, lnfb, h);
    dim3 gHead(VV / 128, NROWS / 128);       // (250, 32)
    sgemm_kernel<<<gHead, 256>>>(h, headW, nullptr, nullptr, out,
                                 NROWS, VV, DD, 0);
}

// round 3
// speedup vs baseline: 2.7076x; 2.7076x over previous
#include <cuda_runtime.h>
#include <math.h>
#include <stdint.h>

// Problem constants
#define BB 4
#define TT 1024
#define VV 32000
#define DD 1024
#define LL 8
#define HH 16
#define NROWS 4096
#define FFD 4096

// ---------------- scratch (device globals: allocation-free rule) ----------
__device__ float g_x[NROWS * DD];
__device__ float g_h[NROWS * DD];
__device__ float g_q[NROWS * DD];
__device__ float g_k[NROWS * DD];
__device__ float g_v[NROWS * DD];
__device__ float g_att[NROWS * DD];
__device__ float g_ff[NROWS * FFD];
// transposed (tf32-rounded) weights, [N,K] K-major
__device__ float g_wqT[LL * DD * DD];
__device__ float g_wkT[LL * DD * DD];
__device__ float g_wvT[LL * DD * DD];
__device__ float g_woT[LL * DD * DD];
__device__ float g_w1T[(size_t)LL * DD * FFD];
__device__ float g_w2T[(size_t)LL * FFD * DD];
__device__ float g_headT[(size_t)VV * DD];

// ---------------- PTX helpers ---------------------------------------------
__device__ __forceinline__ uint32_t smem_u32(const void* p) {
    uint32_t a;
    asm("{ .reg .u64 t; cvta.to.shared.u64 t, %1; cvt.u32.u64 %0, t; }"
        : "=r"(a) : "l"(p));
    return a;
}
__device__ __forceinline__ float to_tf32(float x) {
    asm("cvt.rna.tf32.f32 %0, %0;" : "+f"(x));
    return x;
}
__device__ __forceinline__ void cp16(uint32_t s, const void* g) {
    asm volatile("cp.async.cg.shared.global [%0], [%1], 16;" :: "r"(s), "l"(g));
}
#define CP_COMMIT() asm volatile("cp.async.commit_group;" ::: "memory")
#define CP_WAIT(n) asm volatile("cp.async.wait_group %0;" :: "n"(n) : "memory")

__device__ __forceinline__ void mma_tf32(float* c, const uint32_t* a,
                                         const uint32_t* b) {
    asm volatile(
        "mma.sync.aligned.m16n8k8.row.col.f32.tf32.tf32.f32 "
        "{%0,%1,%2,%3}, {%4,%5,%6,%7}, {%8,%9}, {%0,%1,%2,%3};"
        : "+f"(c[0]), "+f"(c[1]), "+f"(c[2]), "+f"(c[3])
        : "r"(a[0]), "r"(a[1]), "r"(a[2]), "r"(a[3]), "r"(b[0]), "r"(b[1]));
}

// ---------------- embedding ------------------------------------------------
__global__ void embed_kernel(const int* __restrict__ idx,
                             const float* __restrict__ tok,
                             const float* __restrict__ pos,
                             float* __restrict__ x)
{
    int row = blockIdx.x;
    int t = row % TT;
    int id = idx[row];
    int tid = threadIdx.x;
    const float4* tp = (const float4*)(tok + (size_t)id * DD);
    const float4* pp = (const float4*)(pos + (size_t)t * DD);
    float4 a = tp[tid], b = pp[tid];
    float4 o = make_float4(a.x + b.x, a.y + b.y, a.z + b.z, a.w + b.w);
    ((float4*)(x + (size_t)row * DD))[tid] = o;
}

// ---------------- layernorm (tf32-rounded output) --------------------------
__global__ void ln_kernel(const float* __restrict__ x,
                          const float* __restrict__ g,
                          const float* __restrict__ b,
                          float* __restrict__ y)
{
    int row = blockIdx.x;
    int tid = threadIdx.x;
    const float4* xr = (const float4*)(x + (size_t)row * DD);
    float4 v = xr[tid];
    float s  = v.x + v.y + v.z + v.w;
    float sq = v.x * v.x + v.y * v.y + v.z * v.z + v.w * v.w;
#pragma unroll
    for (int o = 16; o > 0; o >>= 1) {
        s  += __shfl_xor_sync(0xffffffffu, s, o);
        sq += __shfl_xor_sync(0xffffffffu, sq, o);
    }
    __shared__ float ss[8], ssq[8];
    int wid = tid >> 5;
    if ((tid & 31) == 0) { ss[wid] = s; ssq[wid] = sq; }
    __syncthreads();
    float S = 0.f, SQ = 0.f;
#pragma unroll
    for (int i = 0; i < 8; i++) { S += ss[i]; SQ += ssq[i]; }
    float mean = S * (1.f / DD);
    float var  = SQ * (1.f / DD) - mean * mean;
    float inv  = rsqrtf(var + 1e-5f);
    float4 gv = ((const float4*)g)[tid];
    float4 bv = ((const float4*)b)[tid];
    float4 o;
    o.x = to_tf32((v.x - mean) * inv * gv.x + bv.x);
    o.y = to_tf32((v.y - mean) * inv * gv.y + bv.y);
    o.z = to_tf32((v.z - mean) * inv * gv.z + bv.z);
    o.w = to_tf32((v.w - mean) * inv * gv.w + bv.w);
    ((float4*)(y + (size_t)row * DD))[tid] = o;
}

// ---------------- weight transpose [K,N] -> [N,K], tf32-rounded ------------
__global__ void transpose_kernel(const float* __restrict__ src,
                                 float* __restrict__ dst, int K, int N)
{
    __shared__ float t[32][33];
    const float* s = src + (size_t)blockIdx.z * K * N;
    float* d = dst + (size_t)blockIdx.z * K * N;
    int n0 = blockIdx.x * 32, k0 = blockIdx.y * 32;
#pragma unroll
    for (int i = threadIdx.y; i < 32; i += 8)
        t[i][threadIdx.x] = s[(size_t)(k0 + i) * N + n0 + threadIdx.x];
    __syncthreads();
#pragma unroll
    for (int i = threadIdx.y; i < 32; i += 8)
        d[(size_t)(n0 + i) * K + k0 + threadIdx.x] = to_tf32(t[threadIdx.x][i]);
}

// ---------------- tf32 mma.sync GEMM ---------------------------------------
// C[M,N] = A[M,K] @ Bt[N,K]^T.  CTA 128x256, 8 warps (2x4), warp tile 64x64.
// BK=32, 4-stage cp.async pipeline. Row pad 36 floats -> conflict-free frags.
#define GF_BIAS  1
#define GF_GELU  2
#define GF_RESID 4
#define BMM 128
#define BNN 256
#define BKK 32
#define APAD 36
#define A_STG (BMM * APAD)           // floats per A stage
#define B_STG (BNN * APAD)
#define STG   (A_STG + B_STG)        // 13824 floats = 55296 B
#define SMEM_BYTES (4 * STG * 4)     // 221184 B

__global__ void __launch_bounds__(256, 1)
tc_gemm(const float* __restrict__ A, const float* __restrict__ Bt,
        const float* __restrict__ bias, const float* __restrict__ resid,
        float* __restrict__ C, int M, int N, int K, int flags)
{
    extern __shared__ float sm[];
    int tid = threadIdx.x;
    int warp = tid >> 5, lane = tid & 31;
    int grp = lane >> 2, tig = lane & 3;
    int row0 = blockIdx.y * BMM, col0 = blockIdx.x * BNN;
    int NIT = K / BKK;
    int m0 = (warp & 1) * 64, n0 = (warp >> 1) * 64;

    uint32_t smb = smem_u32(sm);

    auto load_tile = [&](int slot, int kt) {
        uint32_t ab = smb + slot * (STG * 4);
        uint32_t bb = ab + A_STG * 4;
        int k0 = kt * BKK;
#pragma unroll
        for (int i = 0; i < 4; i++) {
            int lin = i * 256 + tid;
            int m = lin >> 3, j = lin & 7;
            cp16(ab + (m * APAD + j * 4) * 4,
                 A + (size_t)(row0 + m) * K + k0 + j * 4);
        }
#pragma unroll
        for (int i = 0; i < 8; i++) {
            int lin = i * 256 + tid;
            int n = lin >> 3, j = lin & 7;
            cp16(bb + (n * APAD + j * 4) * 4,
                 Bt + (size_t)(col0 + n) * K + k0 + j * 4);
        }
    };

    float acc[4][8][4];
#pragma unroll
    for (int mt = 0; mt < 4; mt++)
#pragma unroll
        for (int nt = 0; nt < 8; nt++)
#pragma unroll
            for (int r = 0; r < 4; r++) acc[mt][nt][r] = 0.f;

    load_tile(0, 0); CP_COMMIT();
    load_tile(1, 1); CP_COMMIT();
    load_tile(2, 2); CP_COMMIT();

    for (int it = 0; it < NIT; it++) {
        int rem = NIT - 1 - it;
        if (rem >= 2)      CP_WAIT(2);
        else if (rem == 1) CP_WAIT(1);
        else               CP_WAIT(0);
        __syncthreads();
        if (it + 3 < NIT) { load_tile((it + 3) & 3, it + 3); CP_COMMIT(); }

        const float* As = sm + (it & 3) * STG;
        const float* Bs = As + A_STG;
#pragma unroll
        for (int kk = 0; kk < 4; kk++) {
            int ks = kk * 8;
            uint32_t af[4][4], bf[8][2];
#pragma unroll
            for (int mt = 0; mt < 4; mt++) {
                int r = m0 + mt * 16 + grp;
                af[mt][0] = __float_as_uint(As[r * APAD + ks + tig]);
                af[mt][1] = __float_as_uint(As[(r + 8) * APAD + ks + tig]);
                af[mt][2] = __float_as_uint(As[r * APAD + ks + tig + 4]);
                af[mt][3] = __float_as_uint(As[(r + 8) * APAD + ks + tig + 4]);
            }
#pragma unroll
            for (int nt = 0; nt < 8; nt++) {
                int c = n0 + nt * 8 + grp;
                bf[nt][0] = __float_as_uint(Bs[c * APAD + ks + tig]);
                bf[nt][1] = __float_as_uint(Bs[c * APAD + ks + tig + 4]);
            }
#pragma unroll
            for (int mt = 0; mt < 4; mt++)
#pragma unroll
                for (int nt = 0; nt < 8; nt++)
                    mma_tf32(acc[mt][nt], af[mt], bf[nt]);
        }
    }

    // ---- epilogue ---------------------------------------------------------
#pragma unroll
    for (int mt = 0; mt < 4; mt++) {
#pragma unroll
        for (int half = 0; half < 2; half++) {
            int r = row0 + m0 + mt * 16 + grp + half * 8;
            float* crow = C + (size_t)r * N;
            const float* rrow = (flags & GF_RESID) ? resid + (size_t)r * N : nullptr;
#pragma unroll
            for (int nt = 0; nt < 8; nt++) {
                int c = col0 + n0 + nt * 8 + 2 * tig;
                float v0 = acc[mt][nt][half * 2 + 0];
                float v1 = acc[mt][nt][half * 2 + 1];
                if (flags & GF_BIAS) { v0 += bias[c]; v1 += bias[c + 1]; }
                if (flags & GF_GELU) {
                    v0 = to_tf32(0.5f * v0 * (1.f + erff(v0 * 0.70710678118654752f)));
                    v1 = to_tf32(0.5f * v1 * (1.f + erff(v1 * 0.70710678118654752f)));
                }
                if (flags & GF_RESID) {
                    float2 rv = *(const float2*)(rrow + c);
                    v0 += rv.x; v1 += rv.y;
                }
                float2 o = make_float2(v0, v1);
                *(float2*)(crow + c) = o;
            }
        }
    }
}

// ---------------- causal attention (per-head, flash-lite) ------------------
__global__ void __launch_bounds__(128, 1) attn_kernel(
    const float* __restrict__ Q, const float* __restrict__ K,
    const float* __restrict__ V, float* __restrict__ O)
{
    __shared__ float Ks[64][68];
    __shared__ float Vs[64][68];

    int bh = blockIdx.y;
    int b = bh >> 4;
    int h = bh & 15;
    int tid = threadIdx.x;
    int qt = blockIdx.x * 128 + tid;

    size_t base = ((size_t)b * TT) * DD + (size_t)h * 64;
    const float* qp = Q + base + (size_t)qt * DD;

    float qreg[64];
#pragma unroll
    for (int i = 0; i < 16; i++)
        *(float4*)&qreg[i * 4] = *(const float4*)(qp + i * 4);

    float acc[64];
#pragma unroll
    for (int d = 0; d < 64; d++) acc[d] = 0.f;
    float m = -1e30f, l = 0.f;
    const float scale = 0.125f;

    int kend = blockIdx.x * 128 + 128;
    for (int kt0 = 0; kt0 < kend; kt0 += 64) {
        int r  = tid >> 1;
        int c0 = (tid & 1) * 32;
        const float* kp = K + base + (size_t)(kt0 + r) * DD + c0;
        const float* vp = V + base + (size_t)(kt0 + r) * DD + c0;
#pragma unroll
        for (int i = 0; i < 8; i++) {
            *(float4*)&Ks[r][c0 + i * 4] = *(const float4*)(kp + i * 4);
            *(float4*)&Vs[r][c0 + i * 4] = *(const float4*)(vp + i * 4);
        }
        __syncthreads();

        int jmax = qt - kt0 + 1;
        if (jmax > 64) jmax = 64;
        for (int j = 0; j < jmax; j++) {
            float s = 0.f;
#pragma unroll
            for (int d = 0; d < 64; d++) s += qreg[d] * Ks[j][d];
            s *= scale;
            if (s <= m) {
                float p = __expf(s - m);
                l += p;
#pragma unroll
                for (int d = 0; d < 64; d++) acc[d] += p * Vs[j][d];
            } else {
                float corr = __expf(m - s);
                l = l * corr + 1.f;
#pragma unroll
                for (int d = 0; d < 64; d++) acc[d] = acc[d] * corr + Vs[j][d];
                m = s;
            }
        }
        __syncthreads();
    }

    float inv = 1.f / l;
    float* op = O + base + (size_t)qt * DD;
#pragma unroll
    for (int d = 0; d < 64; d++) op[d] = to_tf32(acc[d] * inv);
}

// ---------------- host orchestration ---------------------------------------
extern "C" void kernel_launch(void* const* d_in, const int* in_sizes, int n_in,
                              void* d_out, int out_size)
{
    const int*   idx    = (const int*)  d_in[0];
    const float* tok    = (const float*)d_in[1];
    const float* pos    = (const float*)d_in[2];
    const float* ln1g   = (const float*)d_in[3];
    const float* ln1b   = (const float*)d_in[4];
    const float* Wq     = (const float*)d_in[5];
    const float* bq     = (const float*)d_in[6];
    const float* Wk     = (const float*)d_in[7];
    const float* bk     = (const float*)d_in[8];
    const float* Wv     = (const float*)d_in[9];
    const float* bv     = (const float*)d_in[10];
    const float* Wo     = (const float*)d_in[11];
    const float* bo     = (const float*)d_in[12];
    const float* ln2g   = (const float*)d_in[13];
    const float* ln2b   = (const float*)d_in[14];
    const float* W1     = (const float*)d_in[15];
    const float* b1     = (const float*)d_in[16];
    const float* W2     = (const float*)d_in[17];
    const float* b2     = (const float*)d_in[18];
    const float* lnfg   = (const float*)d_in[19];
    const float* lnfb   = (const float*)d_in[20];
    const float* headW  = (const float*)d_in[21];
    float* out = (float*)d_out;

    float *x, *h, *q, *k, *v, *att, *ff;
    float *wqT, *wkT, *wvT, *woT, *w1T, *w2T, *headT;
    cudaGetSymbolAddress((void**)&x,   g_x);
    cudaGetSymbolAddress((void**)&h,   g_h);
    cudaGetSymbolAddress((void**)&q,   g_q);
    cudaGetSymbolAddress((void**)&k,   g_k);
    cudaGetSymbolAddress((void**)&v,   g_v);
    cudaGetSymbolAddress((void**)&att, g_att);
    cudaGetSymbolAddress((void**)&ff,  g_ff);
    cudaGetSymbolAddress((void**)&wqT, g_wqT);
    cudaGetSymbolAddress((void**)&wkT, g_wkT);
    cudaGetSymbolAddress((void**)&wvT, g_wvT);
    cudaGetSymbolAddress((void**)&woT, g_woT);
    cudaGetSymbolAddress((void**)&w1T, g_w1T);
    cudaGetSymbolAddress((void**)&w2T, g_w2T);
    cudaGetSymbolAddress((void**)&headT, g_headT);

    cudaFuncSetAttribute(tc_gemm, cudaFuncAttributeMaxDynamicSharedMemorySize,
                         SMEM_BYTES);

    // weight transposes (tf32-rounded)
    dim3 tb(32, 8);
    transpose_kernel<<<dim3(DD / 32, DD / 32, LL), tb>>>(Wq, wqT, DD, DD);
    transpose_kernel<<<dim3(DD / 32, DD / 32, LL), tb>>>(Wk, wkT, DD, DD);
    transpose_kernel<<<dim3(DD / 32, DD / 32, LL), tb>>>(Wv, wvT, DD, DD);
    transpose_kernel<<<dim3(DD / 32, DD / 32, LL), tb>>>(Wo, woT, DD, DD);
    transpose_kernel<<<dim3(FFD / 32, DD / 32, LL), tb>>>(W1, w1T, DD, FFD);
    transpose_kernel<<<dim3(DD / 32, FFD / 32, LL), tb>>>(W2, w2T, FFD, DD);
    transpose_kernel<<<dim3(VV / 32, DD / 32, 1), tb>>>(headW, headT, DD, VV);

    embed_kernel<<<NROWS, 256>>>(idx, tok, pos, x);

    dim3 gDxD(DD / BNN, NROWS / BMM);        // (4, 32)
    dim3 gDx4D(FFD / BNN, NROWS / BMM);      // (16, 32)
    dim3 gAttn(TT / 128, BB * HH);           // (8, 64)

    for (int l = 0; l < LL; l++) {
        const float* wqT_l = wqT + (size_t)l * DD * DD;
        const float* wkT_l = wkT + (size_t)l * DD * DD;
        const float* wvT_l = wvT + (size_t)l * DD * DD;
        const float* woT_l = woT + (size_t)l * DD * DD;
        const float* w1T_l = w1T + (size_t)l * DD * FFD;
        const float* w2T_l = w2T + (size_t)l * FFD * DD;

        ln_kernel<<<NROWS, 256>>>(x, ln1g + l * DD, ln1b + l * DD, h);
        tc_gemm<<<gDxD, 256, SMEM_BYTES>>>(h, wqT_l, bq + l * DD, nullptr, q,
                                           NROWS, DD, DD, GF_BIAS);
        tc_gemm<<<gDxD, 256, SMEM_BYTES>>>(h, wkT_l, bk + l * DD, nullptr, k,
                                           NROWS, DD, DD, GF_BIAS);
        tc_gemm<<<gDxD, 256, SMEM_BYTES>>>(h, wvT_l, bv + l * DD, nullptr, v,
                                           NROWS, DD, DD, GF_BIAS);
        attn_kernel<<<gAttn, 128>>>(q, k, v, att);
        tc_gemm<<<gDxD, 256, SMEM_BYTES>>>(att, woT_l, bo + l * DD, x, x,
                                           NROWS, DD, DD, GF_BIAS | GF_RESID);
        ln_kernel<<<NROWS, 256>>>(x, ln2g + l * DD, ln2b + l * DD, h);
        tc_gemm<<<gDx4D, 256, SMEM_BYTES>>>(h, w1T_l, b1 + (size_t)l * FFD,
                                            nullptr, ff, NROWS, FFD, DD,
                                            GF_BIAS | GF_GELU);
        tc_gemm<<<gDxD, 256, SMEM_BYTES>>>(ff, w2T_l, b2 + l * DD, x, x,
                                           NROWS, DD, FFD, GF_BIAS | GF_RESID);
    }

    ln_kernel<<<NROWS, 256>>>(x, lnfg, lnfb, h);
    dim3 gHead(VV / BNN, NROWS / BMM);       // (125, 32)
    tc_gemm<<<gHead, 256, SMEM_BYTES>>>(h, headT, nullptr, nullptr, out,
                                        NROWS, VV, DD, 0);
}

// round 4
// speedup vs baseline: 3.6574x; 1.3508x over previous
#include <cuda_runtime.h>
#include <cuda_fp16.h>
#include <math.h>
#include <stdint.h>

// Problem constants
#define BB 4
#define TT 1024
#define VV 32000
#define DD 1024
#define LL 8
#define HH 16
#define NROWS 4096
#define FFD 4096

// ---------------- scratch (device globals: allocation-free rule) ----------
__device__ float  g_x[NROWS * DD];                 // residual stream (fp32)
__device__ __half g_h[NROWS * DD];                 // LN output (gemm A)
__device__ __half g_q[NROWS * DD];
__device__ __half g_k[NROWS * DD];
__device__ __half g_v[NROWS * DD];
__device__ __half g_att[NROWS * DD];
__device__ __half g_ff[NROWS * FFD];
// transposed fp16 weights, [N,K] K-major
__device__ __half g_wqT[LL * DD * DD];
__device__ __half g_wkT[LL * DD * DD];
__device__ __half g_wvT[LL * DD * DD];
__device__ __half g_woT[LL * DD * DD];
__device__ __half g_w1T[(size_t)LL * DD * FFD];
__device__ __half g_w2T[(size_t)LL * FFD * DD];
__device__ __half g_headT[(size_t)VV * DD];

// ---------------- PTX helpers ---------------------------------------------
__device__ __forceinline__ uint32_t smem_u32(const void* p) {
    uint32_t a;
    asm("{ .reg .u64 t; cvta.to.shared.u64 t, %1; cvt.u32.u64 %0, t; }"
        : "=r"(a) : "l"(p));
    return a;
}
__device__ __forceinline__ void cp16(uint32_t s, const void* g) {
    asm volatile("cp.async.cg.shared.global [%0], [%1], 16;" :: "r"(s), "l"(g));
}
#define CP_COMMIT() asm volatile("cp.async.commit_group;" ::: "memory")
#define CP_WAIT(n) asm volatile("cp.async.wait_group %0;" :: "n"(n) : "memory")

__device__ __forceinline__ void mma_f16(float* c, const uint32_t* a,
                                        const uint32_t* b) {
    asm volatile(
        "mma.sync.aligned.m16n8k16.row.col.f32.f16.f16.f32 "
        "{%0,%1,%2,%3}, {%4,%5,%6,%7}, {%8,%9}, {%0,%1,%2,%3};"
        : "+f"(c[0]), "+f"(c[1]), "+f"(c[2]), "+f"(c[3])
        : "r"(a[0]), "r"(a[1]), "r"(a[2]), "r"(a[3]), "r"(b[0]), "r"(b[1]));
}

// ---------------- embedding ------------------------------------------------
__global__ void embed_kernel(const int* __restrict__ idx,
                             const float* __restrict__ tok,
                             const float* __restrict__ pos,
                             float* __restrict__ x)
{
    int row = blockIdx.x;
    int t = row % TT;
    int id = idx[row];
    int tid = threadIdx.x;
    const float4* tp = (const float4*)(tok + (size_t)id * DD);
    const float4* pp = (const float4*)(pos + (size_t)t * DD);
    float4 a = tp[tid], b = pp[tid];
    float4 o = make_float4(a.x + b.x, a.y + b.y, a.z + b.z, a.w + b.w);
    ((float4*)(x + (size_t)row * DD))[tid] = o;
}

// ---------------- layernorm: fp32 in, fp16 out -----------------------------
__global__ void ln_kernel(const float* __restrict__ x,
                          const float* __restrict__ g,
                          const float* __restrict__ b,
                          __half* __restrict__ y)
{
    int row = blockIdx.x;
    int tid = threadIdx.x;
    const float4* xr = (const float4*)(x + (size_t)row * DD);
    float4 v = xr[tid];
    float s  = v.x + v.y + v.z + v.w;
    float sq = v.x * v.x + v.y * v.y + v.z * v.z + v.w * v.w;
#pragma unroll
    for (int o = 16; o > 0; o >>= 1) {
        s  += __shfl_xor_sync(0xffffffffu, s, o);
        sq += __shfl_xor_sync(0xffffffffu, sq, o);
    }
    __shared__ float ss[8], ssq[8];
    int wid = tid >> 5;
    if ((tid & 31) == 0) { ss[wid] = s; ssq[wid] = sq; }
    __syncthreads();
    float S = 0.f, SQ = 0.f;
#pragma unroll
    for (int i = 0; i < 8; i++) { S += ss[i]; SQ += ssq[i]; }
    float mean = S * (1.f / DD);
    float var  = SQ * (1.f / DD) - mean * mean;
    float inv  = rsqrtf(var + 1e-5f);
    float4 gv = ((const float4*)g)[tid];
    float4 bv = ((const float4*)b)[tid];
    __half2* yp = (__half2*)(y + (size_t)row * DD);
    yp[tid * 2]     = __floats2half2_rn((v.x - mean) * inv * gv.x + bv.x,
                                        (v.y - mean) * inv * gv.y + bv.y);
    yp[tid * 2 + 1] = __floats2half2_rn((v.z - mean) * inv * gv.z + bv.z,
                                        (v.w - mean) * inv * gv.w + bv.w);
}

// ---------------- weight transpose [K,N] -> fp16 [N,K] ---------------------
__global__ void transpose_kernel(const float* __restrict__ src,
                                 __half* __restrict__ dst, int K, int N)
{
    __shared__ float t[32][33];
    const float* s = src + (size_t)blockIdx.z * K * N;
    __half* d = dst + (size_t)blockIdx.z * K * N;
    int n0 = blockIdx.x * 32, k0 = blockIdx.y * 32;
#pragma unroll
    for (int i = threadIdx.y; i < 32; i += 8)
        t[i][threadIdx.x] = s[(size_t)(k0 + i) * N + n0 + threadIdx.x];
    __syncthreads();
#pragma unroll
    for (int i = threadIdx.y; i < 32; i += 8)
        d[(size_t)(n0 + i) * K + k0 + threadIdx.x] = __float2half_rn(t[threadIdx.x][i]);
}

// ---------------- fp16 mma.sync GEMM ---------------------------------------
// C[M,N] = A[M,K] @ Bt[N,K]^T. CTA 128x256, 8 warps (2x4), warp tile 64x64.
// BK=32 halves, 4-stage cp.async. PAD=40 halves -> conflict-free fragments.
#define GF_BIAS    1
#define GF_GELU    2
#define GF_RESID   4
#define GF_OUTHALF 8
#define BM 128
#define BN 256
#define BK 32
#define PADH 40
#define A_STGH (BM * PADH)            // 5120 halves
#define B_STGH (BN * PADH)            // 10240 halves
#define STGH   (A_STGH + B_STGH)      // 15360 halves
#define SMEM_BYTES (4 * STGH * 2)     // 122880 B

__global__ void __launch_bounds__(256, 1)
tc_gemm(const __half* __restrict__ A, const __half* __restrict__ Bt,
        const float* __restrict__ bias, const float* __restrict__ resid,
        void* __restrict__ Cout, int M, int N, int K, int flags)
{
    extern __shared__ __half smh[];
    int tid = threadIdx.x;
    int warp = tid >> 5, lane = tid & 31;
    int grp = lane >> 2, tig = lane & 3;
    int row0 = blockIdx.y * BM, col0 = blockIdx.x * BN;
    int NIT = K / BK;
    int m0 = (warp & 1) * 64, n0 = (warp >> 1) * 64;

    uint32_t smb = smem_u32(smh);

    auto load_tile = [&](int slot, int kt) {
        uint32_t ab = smb + slot * (STGH * 2);
        uint32_t bb = ab + A_STGH * 2;
        int k0 = kt * BK;
#pragma unroll
        for (int i = 0; i < 2; i++) {            // A: 512 chunks of 8 halves
            int lin = i * 256 + tid;
            int m = lin >> 2, j = lin & 3;
            cp16(ab + (m * PADH + j * 8) * 2,
                 A + (size_t)(row0 + m) * K + k0 + j * 8);
        }
#pragma unroll
        for (int i = 0; i < 4; i++) {            // B: 1024 chunks
            int lin = i * 256 + tid;
            int n = lin >> 2, j = lin & 3;
            cp16(bb + (n * PADH + j * 8) * 2,
                 Bt + (size_t)(col0 + n) * K + k0 + j * 8);
        }
    };

    float acc[4][8][4];
#pragma unroll
    for (int mt = 0; mt < 4; mt++)
#pragma unroll
        for (int nt = 0; nt < 8; nt++)
#pragma unroll
            for (int r = 0; r < 4; r++) acc[mt][nt][r] = 0.f;

    load_tile(0, 0); CP_COMMIT();
    load_tile(1, 1); CP_COMMIT();
    load_tile(2, 2); CP_COMMIT();

    for (int it = 0; it < NIT; it++) {
        int rem = NIT - 1 - it;
        if (rem >= 2)      CP_WAIT(2);
        else if (rem == 1) CP_WAIT(1);
        else               CP_WAIT(0);
        __syncthreads();
        if (it + 3 < NIT) { load_tile((it + 3) & 3, it + 3); CP_COMMIT(); }

        const uint32_t* As32 = (const uint32_t*)(smh + (size_t)(it & 3) * STGH);
        const uint32_t* Bs32 = As32 + A_STGH / 2;
#pragma unroll
        for (int kk = 0; kk < 2; kk++) {         // two k16 steps per BK=32
            int ks2 = kk * 8;                    // in u32 units
            uint32_t af[4][4], bf[8][2];
#pragma unroll
            for (int mt = 0; mt < 4; mt++) {
                int r = m0 + mt * 16 + grp;
                af[mt][0] = As32[r * 20 + ks2 + tig];
                af[mt][1] = As32[(r + 8) * 20 + ks2 + tig];
                af[mt][2] = As32[r * 20 + ks2 + tig + 4];
                af[mt][3] = As32[(r + 8) * 20 + ks2 + tig + 4];
            }
#pragma unroll
            for (int nt = 0; nt < 8; nt++) {
                int c = n0 + nt * 8 + grp;
                bf[nt][0] = Bs32[c * 20 + ks2 + tig];
                bf[nt][1] = Bs32[c * 20 + ks2 + tig + 4];
            }
#pragma unroll
            for (int mt = 0; mt < 4; mt++)
#pragma unroll
                for (int nt = 0; nt < 8; nt++)
                    mma_f16(acc[mt][nt], af[mt], bf[nt]);
        }
    }

    // ---- epilogue ---------------------------------------------------------
#pragma unroll
    for (int mt = 0; mt < 4; mt++) {
#pragma unroll
        for (int half = 0; half < 2; half++) {
            int r = row0 + m0 + mt * 16 + grp + half * 8;
            const float* rrow = (flags & GF_RESID) ? resid + (size_t)r * N : nullptr;
#pragma unroll
            for (int nt = 0; nt < 8; nt++) {
                int c = col0 + n0 + nt * 8 + 2 * tig;
                float v0 = acc[mt][nt][half * 2 + 0];
                float v1 = acc[mt][nt][half * 2 + 1];
                if (flags & GF_BIAS) { v0 += bias[c]; v1 += bias[c + 1]; }
                if (flags & GF_GELU) {
                    v0 = 0.5f * v0 * (1.f + erff(v0 * 0.70710678118654752f));
                    v1 = 0.5f * v1 * (1.f + erff(v1 * 0.70710678118654752f));
                }
                if (flags & GF_RESID) {
                    float2 rv = *(const float2*)(rrow + c);
                    v0 += rv.x; v1 += rv.y;
                }
                if (flags & GF_OUTHALF) {
                    *(__half2*)((__half*)Cout + (size_t)r * N + c) =
                        __floats2half2_rn(v0, v1);
                } else {
                    *(float2*)((float*)Cout + (size_t)r * N + c) =
                        make_float2(v0, v1);
                }
            }
        }
    }
}

// ---------------- causal attention (fp16 in/out, fp32 compute) -------------
__global__ void __launch_bounds__(128, 1) attn_kernel(
    const __half* __restrict__ Q, const __half* __restrict__ K,
    const __half* __restrict__ V, __half* __restrict__ O)
{
    __shared__ float Ks[64][68];
    __shared__ float Vs[64][68];

    int bh = blockIdx.y;
    int b = bh >> 4;
    int h = bh & 15;
    int tid = threadIdx.x;
    int qt = blockIdx.x * 128 + tid;

    size_t base = ((size_t)b * TT) * DD + (size_t)h * 64;
    const __half* qp = Q + base + (size_t)qt * DD;

    float qreg[64];
    {
        const uint4* q4 = (const uint4*)qp;      // 8 halves per uint4
#pragma unroll
        for (int i = 0; i < 8; i++) {
            uint4 u = q4[i];
            const __half2* hp = (const __half2*)&u;
#pragma unroll
            for (int j = 0; j < 4; j++) {
                float2 f = __half22float2(hp[j]);
                qreg[i * 8 + j * 2] = f.x;
                qreg[i * 8 + j * 2 + 1] = f.y;
            }
        }
    }

    float acc[64];
#pragma unroll
    for (int d = 0; d < 64; d++) acc[d] = 0.f;
    float m = -1e30f, l = 0.f;
    const float scale = 0.125f;

    int kend = blockIdx.x * 128 + 128;
    for (int kt0 = 0; kt0 < kend; kt0 += 64) {
        int r  = tid >> 1;
        int c0 = (tid & 1) * 32;
        const uint4* kp = (const uint4*)(K + base + (size_t)(kt0 + r) * DD + c0);
        const uint4* vp = (const uint4*)(V + base + (size_t)(kt0 + r) * DD + c0);
#pragma unroll
        for (int i = 0; i < 4; i++) {
            uint4 uk = kp[i], uv = vp[i];
            const __half2* hk = (const __half2*)&uk;
            const __half2* hv = (const __half2*)&uv;
#pragma unroll
            for (int j = 0; j < 4; j++) {
                float2 fk = __half22float2(hk[j]);
                float2 fv = __half22float2(hv[j]);
                Ks[r][c0 + i * 8 + j * 2] = fk.x;
                Ks[r][c0 + i * 8 + j * 2 + 1] = fk.y;
                Vs[r][c0 + i * 8 + j * 2] = fv.x;
                Vs[r][c0 + i * 8 + j * 2 + 1] = fv.y;
            }
        }
        __syncthreads();

        int jmax = qt - kt0 + 1;
        if (jmax > 64) jmax = 64;
        for (int j = 0; j < jmax; j++) {
            float s = 0.f;
#pragma unroll
            for (int d = 0; d < 64; d++) s += qreg[d] * Ks[j][d];
            s *= scale;
            if (s <= m) {
                float p = __expf(s - m);
                l += p;
#pragma unroll
                for (int d = 0; d < 64; d++) acc[d] += p * Vs[j][d];
            } else {
                float corr = __expf(m - s);
                l = l * corr + 1.f;
#pragma unroll
                for (int d = 0; d < 64; d++) acc[d] = acc[d] * corr + Vs[j][d];
                m = s;
            }
        }
        __syncthreads();
    }

    float inv = 1.f / l;
    __half2* op = (__half2*)(O + base + (size_t)qt * DD);
#pragma unroll
    for (int d = 0; d < 32; d++)
        op[d] = __floats2half2_rn(acc[2 * d] * inv, acc[2 * d + 1] * inv);
}

// ---------------- host orchestration ---------------------------------------
extern "C" void kernel_launch(void* const* d_in, const int* in_sizes, int n_in,
                              void* d_out, int out_size)
{
    const int*   idx    = (const int*)  d_in[0];
    const float* tok    = (const float*)d_in[1];
    const float* pos    = (const float*)d_in[2];
    const float* ln1g   = (const float*)d_in[3];
    const float* ln1b   = (const float*)d_in[4];
    const float* Wq     = (const float*)d_in[5];
    const float* bq     = (const float*)d_in[6];
    const float* Wk     = (const float*)d_in[7];
    const float* bk     = (const float*)d_in[8];
    const float* Wv     = (const float*)d_in[9];
    const float* bv     = (const float*)d_in[10];
    const float* Wo     = (const float*)d_in[11];
    const float* bo     = (const float*)d_in[12];
    const float* ln2g   = (const float*)d_in[13];
    const float* ln2b   = (const float*)d_in[14];
    const float* W1     = (const float*)d_in[15];
    const float* b1     = (const float*)d_in[16];
    const float* W2     = (const float*)d_in[17];
    const float* b2     = (const float*)d_in[18];
    const float* lnfg   = (const float*)d_in[19];
    const float* lnfb   = (const float*)d_in[20];
    const float* headW  = (const float*)d_in[21];
    float* out = (float*)d_out;

    float *x;
    __half *h, *q, *k, *v, *att, *ff;
    __half *wqT, *wkT, *wvT, *woT, *w1T, *w2T, *headT;
    cudaGetSymbolAddress((void**)&x,   g_x);
    cudaGetSymbolAddress((void**)&h,   g_h);
    cudaGetSymbolAddress((void**)&q,   g_q);
    cudaGetSymbolAddress((void**)&k,   g_k);
    cudaGetSymbolAddress((void**)&v,   g_v);
    cudaGetSymbolAddress((void**)&att, g_att);
    cudaGetSymbolAddress((void**)&ff,  g_ff);
    cudaGetSymbolAddress((void**)&wqT, g_wqT);
    cudaGetSymbolAddress((void**)&wkT, g_wkT);
    cudaGetSymbolAddress((void**)&wvT, g_wvT);
    cudaGetSymbolAddress((void**)&woT, g_woT);
    cudaGetSymbolAddress((void**)&w1T, g_w1T);
    cudaGetSymbolAddress((void**)&w2T, g_w2T);
    cudaGetSymbolAddress((void**)&headT, g_headT);

    cudaFuncSetAttribute(tc_gemm, cudaFuncAttributeMaxDynamicSharedMemorySize,
                         SMEM_BYTES);

    // weight transposes (fp32 -> fp16 [N,K])
    dim3 tb(32, 8);
    transpose_kernel<<<dim3(DD / 32, DD / 32, LL), tb>>>(Wq, wqT, DD, DD);
    transpose_kernel<<<dim3(DD / 32, DD / 32, LL), tb>>>(Wk, wkT, DD, DD);
    transpose_kernel<<<dim3(DD / 32, DD / 32, LL), tb>>>(Wv, wvT, DD, DD);
    transpose_kernel<<<dim3(DD / 32, DD / 32, LL), tb>>>(Wo, woT, DD, DD);
    transpose_kernel<<<dim3(FFD / 32, DD / 32, LL), tb>>>(W1, w1T, DD, FFD);
    transpose_kernel<<<dim3(DD / 32, FFD / 32, LL), tb>>>(W2, w2T, FFD, DD);
    transpose_kernel<<<dim3(VV / 32, DD / 32, 1), tb>>>(headW, headT, DD, VV);

    embed_kernel<<<NROWS, 256>>>(idx, tok, pos, x);

    dim3 gDxD(DD / BN, NROWS / BM);          // (4, 32)
    dim3 gDx4D(FFD / BN, NROWS / BM);        // (16, 32)
    dim3 gAttn(TT / 128, BB * HH);           // (8, 64)

    for (int l = 0; l < LL; l++) {
        const __half* wqT_l = wqT + (size_t)l * DD * DD;
        const __half* wkT_l = wkT + (size_t)l * DD * DD;
        const __half* wvT_l = wvT + (size_t)l * DD * DD;
        const __half* woT_l = woT + (size_t)l * DD * DD;
        const __half* w1T_l = w1T + (size_t)l * DD * FFD;
        const __half* w2T_l = w2T + (size_t)l * FFD * DD;

        ln_kernel<<<NROWS, 256>>>(x, ln1g + l * DD, ln1b + l * DD, h);
        tc_gemm<<<gDxD, 256, SMEM_BYTES>>>(h, wqT_l, bq + l * DD, nullptr, q,
                                           NROWS, DD, DD, GF_BIAS | GF_OUTHALF);
        tc_gemm<<<gDxD, 256, SMEM_BYTES>>>(h, wkT_l, bk + l * DD, nullptr, k,
                                           NROWS, DD, DD, GF_BIAS | GF_OUTHALF);
        tc_gemm<<<gDxD, 256, SMEM_BYTES>>>(h, wvT_l, bv + l * DD, nullptr, v,
                                           NROWS, DD, DD, GF_BIAS | GF_OUTHALF);
        attn_kernel<<<gAttn, 128>>>(q, k, v, att);
        tc_gemm<<<gDxD, 256, SMEM_BYTES>>>(att, woT_l, bo + l * DD, x, x,
                                           NROWS, DD, DD, GF_BIAS | GF_RESID);
        ln_kernel<<<NROWS, 256>>>(x, ln2g + l * DD, ln2b + l * DD, h);
        tc_gemm<<<gDx4D, 256, SMEM_BYTES>>>(h, w1T_l, b1 + (size_t)l * FFD,
                                            nullptr, ff, NROWS, FFD, DD,
                                            GF_BIAS | GF_GELU | GF_OUTHALF);
        tc_gemm<<<gDxD, 256, SMEM_BYTES>>>(ff, w2T_l, b2 + l * DD, x, x,
                                           NROWS, DD, FFD, GF_BIAS | GF_RESID);
    }

    ln_kernel<<<NROWS, 256>>>(x, lnfg, lnfb, h);
    dim3 gHead(VV / BN, NROWS / BM);         // (125, 32)
    tc_gemm<<<gHead, 256, SMEM_BYTES>>>(h, headT, nullptr, nullptr, out,
                                        NROWS, VV, DD, 0);
}

// round 5
// speedup vs baseline: 5.6243x; 1.5378x over previous
#include <cuda_runtime.h>
#include <cuda_fp16.h>
#include <math.h>
#include <stdint.h>

// Problem constants
#define BB 4
#define TT 1024
#define VV 32000
#define DD 1024
#define LL 8
#define HH 16
#define NROWS 4096
#define FFD 4096

// ---------------- scratch (device globals: allocation-free rule) ----------
__device__ float  g_x[NROWS * DD];                 // residual stream (fp32)
__device__ __half g_h[NROWS * DD];
__device__ __half g_q[NROWS * DD];
__device__ __half g_k[NROWS * DD];
__device__ __half g_v[NROWS * DD];
__device__ __half g_att[NROWS * DD];
__device__ __half g_ff[NROWS * FFD];
__device__ __half g_wqT[LL * DD * DD];
__device__ __half g_wkT[LL * DD * DD];
__device__ __half g_wvT[LL * DD * DD];
__device__ __half g_woT[LL * DD * DD];
__device__ __half g_w1T[(size_t)LL * DD * FFD];
__device__ __half g_w2T[(size_t)LL * FFD * DD];
__device__ __half g_headT[(size_t)VV * DD];

// ---------------- PTX helpers ---------------------------------------------
__device__ __forceinline__ uint32_t smem_u32(const void* p) {
    uint32_t a;
    asm("{ .reg .u64 t; cvta.to.shared.u64 t, %1; cvt.u32.u64 %0, t; }"
        : "=r"(a) : "l"(p));
    return a;
}
__device__ __forceinline__ void cp16(uint32_t s, const void* g) {
    asm volatile("cp.async.cg.shared.global [%0], [%1], 16;" :: "r"(s), "l"(g));
}
#define CP_COMMIT() asm volatile("cp.async.commit_group;" ::: "memory")
#define CP_WAIT(n) asm volatile("cp.async.wait_group %0;" :: "n"(n) : "memory")

__device__ __forceinline__ void mma_f16(float* c, const uint32_t* a,
                                        const uint32_t* b) {
    asm volatile(
        "mma.sync.aligned.m16n8k16.row.col.f32.f16.f16.f32 "
        "{%0,%1,%2,%3}, {%4,%5,%6,%7}, {%8,%9}, {%0,%1,%2,%3};"
        : "+f"(c[0]), "+f"(c[1]), "+f"(c[2]), "+f"(c[3])
        : "r"(a[0]), "r"(a[1]), "r"(a[2]), "r"(a[3]), "r"(b[0]), "r"(b[1]));
}
__device__ __forceinline__ void ldsm4(uint32_t* r, uint32_t addr) {
    asm volatile("ldmatrix.sync.aligned.m8n8.x4.shared.b16 {%0,%1,%2,%3}, [%4];"
        : "=r"(r[0]), "=r"(r[1]), "=r"(r[2]), "=r"(r[3]) : "r"(addr));
}

// ---------------- embedding ------------------------------------------------
__global__ void embed_kernel(const int* __restrict__ idx,
                             const float* __restrict__ tok,
                             const float* __restrict__ pos,
                             float* __restrict__ x)
{
    int row = blockIdx.x;
    int t = row % TT;
    int id = idx[row];
    int tid = threadIdx.x;
    const float4* tp = (const float4*)(tok + (size_t)id * DD);
    const float4* pp = (const float4*)(pos + (size_t)t * DD);
    float4 a = tp[tid], b = pp[tid];
    float4 o = make_float4(a.x + b.x, a.y + b.y, a.z + b.z, a.w + b.w);
    ((float4*)(x + (size_t)row * DD))[tid] = o;
}

// ---------------- layernorm: fp32 in, fp16 out -----------------------------
__global__ void ln_kernel(const float* __restrict__ x,
                          const float* __restrict__ g,
                          const float* __restrict__ b,
                          __half* __restrict__ y)
{
    int row = blockIdx.x;
    int tid = threadIdx.x;
    const float4* xr = (const float4*)(x + (size_t)row * DD);
    float4 v = xr[tid];
    float s  = v.x + v.y + v.z + v.w;
    float sq = v.x * v.x + v.y * v.y + v.z * v.z + v.w * v.w;
#pragma unroll
    for (int o = 16; o > 0; o >>= 1) {
        s  += __shfl_xor_sync(0xffffffffu, s, o);
        sq += __shfl_xor_sync(0xffffffffu, sq, o);
    }
    __shared__ float ss[8], ssq[8];
    int wid = tid >> 5;
    if ((tid & 31) == 0) { ss[wid] = s; ssq[wid] = sq; }
    __syncthreads();
    float S = 0.f, SQ = 0.f;
#pragma unroll
    for (int i = 0; i < 8; i++) { S += ss[i]; SQ += ssq[i]; }
    float mean = S * (1.f / DD);
    float var  = SQ * (1.f / DD) - mean * mean;
    float inv  = rsqrtf(var + 1e-5f);
    float4 gv = ((const float4*)g)[tid];
    float4 bv = ((const float4*)b)[tid];
    __half2* yp = (__half2*)(y + (size_t)row * DD);
    yp[tid * 2]     = __floats2half2_rn((v.x - mean) * inv * gv.x + bv.x,
                                        (v.y - mean) * inv * gv.y + bv.y);
    yp[tid * 2 + 1] = __floats2half2_rn((v.z - mean) * inv * gv.z + bv.z,
                                        (v.w - mean) * inv * gv.w + bv.w);
}

// ---------------- weight transpose [K,N] -> fp16 [N,K] ---------------------
__global__ void transpose_kernel(const float* __restrict__ src,
                                 __half* __restrict__ dst, int K, int N)
{
    __shared__ float t[32][33];
    const float* s = src + (size_t)blockIdx.z * K * N;
    __half* d = dst + (size_t)blockIdx.z * K * N;
    int n0 = blockIdx.x * 32, k0 = blockIdx.y * 32;
#pragma unroll
    for (int i = threadIdx.y; i < 32; i += 8)
        t[i][threadIdx.x] = s[(size_t)(k0 + i) * N + n0 + threadIdx.x];
    __syncthreads();
#pragma unroll
    for (int i = threadIdx.y; i < 32; i += 8)
        d[(size_t)(n0 + i) * K + k0 + threadIdx.x] = __float2half_rn(t[threadIdx.x][i]);
}

// ---------------- fp16 mma.sync GEMM (ldmatrix fragments) ------------------
#define GF_BIAS    1
#define GF_GELU    2
#define GF_RESID   4
#define GF_OUTHALF 8
#define BM 128
#define BN 256
#define BK 32
#define PADH 40
#define A_STGH (BM * PADH)
#define B_STGH (BN * PADH)
#define STGH   (A_STGH + B_STGH)
#define SMEM_BYTES (4 * STGH * 2)     // 122880 B

__global__ void __launch_bounds__(256, 1)
tc_gemm(const __half* __restrict__ A, const __half* __restrict__ Bt,
        const float* __restrict__ bias, const float* __restrict__ resid,
        void* __restrict__ Cout, int M, int N, int K, int flags)
{
    extern __shared__ __half smh[];
    int tid = threadIdx.x;
    int warp = tid >> 5, lane = tid & 31;
    int grp = lane >> 2, tig = lane & 3;
    int row0 = blockIdx.y * BM, col0 = blockIdx.x * BN;
    int NIT = K / BK;
    int m0 = (warp & 1) * 64, n0 = (warp >> 1) * 64;

    uint32_t smb = smem_u32(smh);

    auto load_tile = [&](int slot, int kt) {
        uint32_t ab = smb + slot * (STGH * 2);
        uint32_t bb = ab + A_STGH * 2;
        int k0 = kt * BK;
#pragma unroll
        for (int i = 0; i < 2; i++) {
            int lin = i * 256 + tid;
            int m = lin >> 2, j = lin & 3;
            cp16(ab + (m * PADH + j * 8) * 2,
                 A + (size_t)(row0 + m) * K + k0 + j * 8);
        }
#pragma unroll
        for (int i = 0; i < 4; i++) {
            int lin = i * 256 + tid;
            int n = lin >> 2, j = lin & 3;
            cp16(bb + (n * PADH + j * 8) * 2,
                 Bt + (size_t)(col0 + n) * K + k0 + j * 8);
        }
    };

    float acc[4][8][4];
#pragma unroll
    for (int mt = 0; mt < 4; mt++)
#pragma unroll
        for (int nt = 0; nt < 8; nt++)
#pragma unroll
            for (int r = 0; r < 4; r++) acc[mt][nt][r] = 0.f;

    // per-lane ldmatrix base offsets (halves -> bytes)
    uint32_t a_off = (uint32_t)(((m0 + (lane & 7) + 8 * ((lane >> 3) & 1)) * PADH
                     + 8 * ((lane >> 4) & 1)) * 2);
    uint32_t b_off = (uint32_t)(A_STGH * 2 +
                     ((n0 + (lane & 7) + 8 * ((lane >> 4) & 1)) * PADH
                     + 8 * ((lane >> 3) & 1)) * 2);

    load_tile(0, 0); CP_COMMIT();
    load_tile(1, 1); CP_COMMIT();
    load_tile(2, 2); CP_COMMIT();

    for (int it = 0; it < NIT; it++) {
        int rem = NIT - 1 - it;
        if (rem >= 2)      CP_WAIT(2);
        else if (rem == 1) CP_WAIT(1);
        else               CP_WAIT(0);
        __syncthreads();
        if (it + 3 < NIT) { load_tile((it + 3) & 3, it + 3); CP_COMMIT(); }

        uint32_t stage = smb + (it & 3) * (STGH * 2);
#pragma unroll
        for (int kk = 0; kk < 2; kk++) {
            uint32_t af[4][4], bq[4][4];
#pragma unroll
            for (int mt = 0; mt < 4; mt++)
                ldsm4(af[mt], stage + a_off + (mt * 16 * PADH + kk * 16) * 2);
#pragma unroll
            for (int nt2 = 0; nt2 < 4; nt2++)
                ldsm4(bq[nt2], stage + b_off + (nt2 * 16 * PADH + kk * 16) * 2);
#pragma unroll
            for (int mt = 0; mt < 4; mt++)
#pragma unroll
                for (int nt = 0; nt < 8; nt++)
                    mma_f16(acc[mt][nt], af[mt], &bq[nt >> 1][(nt & 1) * 2]);
        }
    }

    // ---- epilogue ---------------------------------------------------------
#pragma unroll
    for (int mt = 0; mt < 4; mt++) {
#pragma unroll
        for (int half = 0; half < 2; half++) {
            int r = row0 + m0 + mt * 16 + grp + half * 8;
            const float* rrow = (flags & GF_RESID) ? resid + (size_t)r * N : nullptr;
#pragma unroll
            for (int nt = 0; nt < 8; nt++) {
                int c = col0 + n0 + nt * 8 + 2 * tig;
                float v0 = acc[mt][nt][half * 2 + 0];
                float v1 = acc[mt][nt][half * 2 + 1];
                if (flags & GF_BIAS) { v0 += bias[c]; v1 += bias[c + 1]; }
                if (flags & GF_GELU) {
                    v0 = 0.5f * v0 * (1.f + erff(v0 * 0.70710678118654752f));
                    v1 = 0.5f * v1 * (1.f + erff(v1 * 0.70710678118654752f));
                }
                if (flags & GF_RESID) {
                    float2 rv = *(const float2*)(rrow + c);
                    v0 += rv.x; v1 += rv.y;
                }
                if (flags & GF_OUTHALF) {
                    *(__half2*)((__half*)Cout + (size_t)r * N + c) =
                        __floats2half2_rn(v0, v1);
                } else {
                    *(float2*)((float*)Cout + (size_t)r * N + c) =
                        make_float2(v0, v1);
                }
            }
        }
    }
}

// ---------------- tensor-core flash attention ------------------------------
// CTA: 64 queries (4 warps x 16 rows), KV blocks of 64, head dim 64.
__global__ void __launch_bounds__(128, 1) fa_kernel(
    const __half* __restrict__ Q, const __half* __restrict__ K,
    const __half* __restrict__ V, __half* __restrict__ O)
{
    __shared__ __half Qs[64][72];
    __shared__ __half Ks[64][72];
    __shared__ __half Vt[64][72];     // V transposed: [dim][key]

    int tid = threadIdx.x;
    int warp = tid >> 5, lane = tid & 31;
    int grp = lane >> 2, tig = lane & 3;
    int bh = blockIdx.y;
    int b = bh >> 4, h = bh & 15;
    int q0 = blockIdx.x * 64;

    size_t base = ((size_t)b * TT) * DD + (size_t)h * 64;

    // stage Q (scaled by 1/sqrt(64) = 0.125)
    const __half2 sc2 = __floats2half2_rn(0.125f, 0.125f);
    for (int i = tid; i < 64 * 8; i += 128) {
        int row = i >> 3, c8 = (i & 7) * 8;
        uint4 u = *(const uint4*)(Q + base + (size_t)(q0 + row) * DD + c8);
        __half2* hp = (__half2*)&u;
#pragma unroll
        for (int j = 0; j < 4; j++) hp[j] = __hmul2(hp[j], sc2);
        *(uint4*)&Qs[row][c8] = u;
    }
    __syncthreads();

    // Q fragments: aq[kstep s][4]
    uint32_t aq[4][4];
    int mrow = warp * 16;
#pragma unroll
    for (int s = 0; s < 4; s++) {
        aq[s][0] = *(const uint32_t*)&Qs[mrow + grp][16 * s + 2 * tig];
        aq[s][1] = *(const uint32_t*)&Qs[mrow + grp + 8][16 * s + 2 * tig];
        aq[s][2] = *(const uint32_t*)&Qs[mrow + grp][16 * s + 2 * tig + 8];
        aq[s][3] = *(const uint32_t*)&Qs[mrow + grp + 8][16 * s + 2 * tig + 8];
    }

    float o[8][4];
#pragma unroll
    for (int d = 0; d < 8; d++)
#pragma unroll
        for (int r = 0; r < 4; r++) o[d][r] = 0.f;
    float m0v = -1e30f, m1v = -1e30f, l0 = 0.f, l1 = 0.f;

    for (int kt0 = 0; kt0 <= q0; kt0 += 64) {
        __syncthreads();   // protect Ks/Vt reuse from previous iteration
        // stage K
        for (int i = tid; i < 64 * 8; i += 128) {
            int row = i >> 3, c8 = (i & 7) * 8;
            *(uint4*)&Ks[row][c8] =
                *(const uint4*)(K + base + (size_t)(kt0 + row) * DD + c8);
        }
        // stage V transposed
        for (int i = tid; i < 64 * 32; i += 128) {
            int row = i & 63, cp = i >> 6;   // cp: 0..31 half2 pairs
            __half2 v = *(const __half2*)(V + base + (size_t)(kt0 + row) * DD + cp * 2);
            Vt[cp * 2][row] = __low2half(v);
            Vt[cp * 2 + 1][row] = __high2half(v);
        }
        __syncthreads();

        // S = Q K^T  (scale folded into Q)
        float sc[8][4];
#pragma unroll
        for (int j = 0; j < 8; j++)
#pragma unroll
            for (int r = 0; r < 4; r++) sc[j][r] = 0.f;
#pragma unroll
        for (int s = 0; s < 4; s++) {
#pragma unroll
            for (int j = 0; j < 8; j++) {
                uint32_t bf[2];
                bf[0] = *(const uint32_t*)&Ks[8 * j + grp][16 * s + 2 * tig];
                bf[1] = *(const uint32_t*)&Ks[8 * j + grp][16 * s + 2 * tig + 8];
                mma_f16(sc[j], aq[s], bf);
            }
        }

        // causal mask (only on diagonal block)
        if (kt0 == q0) {
            int lq0 = mrow + grp, lq1 = mrow + grp + 8;
#pragma unroll
            for (int j = 0; j < 8; j++) {
                int lk = 8 * j + 2 * tig;
                if (lk > lq0)     sc[j][0] = -1e30f;
                if (lk + 1 > lq0) sc[j][1] = -1e30f;
                if (lk > lq1)     sc[j][2] = -1e30f;
                if (lk + 1 > lq1) sc[j][3] = -1e30f;
            }
        }

        // row max (quad reduce)
        float mx0 = -1e30f, mx1 = -1e30f;
#pragma unroll
        for (int j = 0; j < 8; j++) {
            mx0 = fmaxf(mx0, fmaxf(sc[j][0], sc[j][1]));
            mx1 = fmaxf(mx1, fmaxf(sc[j][2], sc[j][3]));
        }
        mx0 = fmaxf(mx0, __shfl_xor_sync(0xffffffffu, mx0, 1));
        mx0 = fmaxf(mx0, __shfl_xor_sync(0xffffffffu, mx0, 2));
        mx1 = fmaxf(mx1, __shfl_xor_sync(0xffffffffu, mx1, 1));
        mx1 = fmaxf(mx1, __shfl_xor_sync(0xffffffffu, mx1, 2));

        float mn0 = fmaxf(m0v, mx0), mn1 = fmaxf(m1v, mx1);
        float cr0 = __expf(m0v - mn0), cr1 = __expf(m1v - mn1);
        m0v = mn0; m1v = mn1;

        // P = exp(S - m), fp16 A-fragments + row sums
        uint32_t ap[4][4];
        float rs0 = 0.f, rs1 = 0.f;
#pragma unroll
        for (int j = 0; j < 8; j++) {
            float p0 = __expf(sc[j][0] - mn0);
            float p1 = __expf(sc[j][1] - mn0);
            float p2 = __expf(sc[j][2] - mn1);
            float p3 = __expf(sc[j][3] - mn1);
            rs0 += p0 + p1; rs1 += p2 + p3;
            int s = j >> 1, odd = j & 1;
            __half2 h01 = __floats2half2_rn(p0, p1);
            __half2 h23 = __floats2half2_rn(p2, p3);
            ap[s][odd * 2 + 0] = *(uint32_t*)&h01;
            ap[s][odd * 2 + 1] = *(uint32_t*)&h23;
        }
        rs0 += __shfl_xor_sync(0xffffffffu, rs0, 1);
        rs0 += __shfl_xor_sync(0xffffffffu, rs0, 2);
        rs1 += __shfl_xor_sync(0xffffffffu, rs1, 1);
        rs1 += __shfl_xor_sync(0xffffffffu, rs1, 2);
        l0 = l0 * cr0 + rs0;
        l1 = l1 * cr1 + rs1;

#pragma unroll
        for (int d = 0; d < 8; d++) {
            o[d][0] *= cr0; o[d][1] *= cr0;
            o[d][2] *= cr1; o[d][3] *= cr1;
        }

        // O += P V
#pragma unroll
        for (int s = 0; s < 4; s++) {
#pragma unroll
            for (int d = 0; d < 8; d++) {
                uint32_t bf[2];
                bf[0] = *(const uint32_t*)&Vt[8 * d + grp][16 * s + 2 * tig];
                bf[1] = *(const uint32_t*)&Vt[8 * d + grp][16 * s + 2 * tig + 8];
                mma_f16(o[d], ap[s], bf);
            }
        }
    }

    float i0 = 1.f / l0, i1 = 1.f / l1;
    int r0 = q0 + mrow + grp, r1 = r0 + 8;
#pragma unroll
    for (int d = 0; d < 8; d++) {
        int c = 8 * d + 2 * tig;
        *(__half2*)(O + base + (size_t)r0 * DD + c) =
            __floats2half2_rn(o[d][0] * i0, o[d][1] * i0);
        *(__half2*)(O + base + (size_t)r1 * DD + c) =
            __floats2half2_rn(o[d][2] * i1, o[d][3] * i1);
    }
}

// ---------------- host orchestration ---------------------------------------
extern "C" void kernel_launch(void* const* d_in, const int* in_sizes, int n_in,
                              void* d_out, int out_size)
{
    const int*   idx    = (const int*)  d_in[0];
    const float* tok    = (const float*)d_in[1];
    const float* pos    = (const float*)d_in[2];
    const float* ln1g   = (const float*)d_in[3];
    const float* ln1b   = (const float*)d_in[4];
    const float* Wq     = (const float*)d_in[5];
    const float* bq     = (const float*)d_in[6];
    const float* Wk     = (const float*)d_in[7];
    const float* bk     = (const float*)d_in[8];
    const float* Wv     = (const float*)d_in[9];
    const float* bv     = (const float*)d_in[10];
    const float* Wo     = (const float*)d_in[11];
    const float* bo     = (const float*)d_in[12];
    const float* ln2g   = (const float*)d_in[13];
    const float* ln2b   = (const float*)d_in[14];
    const float* W1     = (const float*)d_in[15];
    const float* b1     = (const float*)d_in[16];
    const float* W2     = (const float*)d_in[17];
    const float* b2     = (const float*)d_in[18];
    const float* lnfg   = (const float*)d_in[19];
    const float* lnfb   = (const float*)d_in[20];
    const float* headW  = (const float*)d_in[21];
    float* out = (float*)d_out;

    float *x;
    __half *h, *q, *k, *v, *att, *ff;
    __half *wqT, *wkT, *wvT, *woT, *w1T, *w2T, *headT;
    cudaGetSymbolAddress((void**)&x,   g_x);
    cudaGetSymbolAddress((void**)&h,   g_h);
    cudaGetSymbolAddress((void**)&q,   g_q);
    cudaGetSymbolAddress((void**)&k,   g_k);
    cudaGetSymbolAddress((void**)&v,   g_v);
    cudaGetSymbolAddress((void**)&att, g_att);
    cudaGetSymbolAddress((void**)&ff,  g_ff);
    cudaGetSymbolAddress((void**)&wqT, g_wqT);
    cudaGetSymbolAddress((void**)&wkT, g_wkT);
    cudaGetSymbolAddress((void**)&wvT, g_wvT);
    cudaGetSymbolAddress((void**)&woT, g_woT);
    cudaGetSymbolAddress((void**)&w1T, g_w1T);
    cudaGetSymbolAddress((void**)&w2T, g_w2T);
    cudaGetSymbolAddress((void**)&headT, g_headT);

    cudaFuncSetAttribute(tc_gemm, cudaFuncAttributeMaxDynamicSharedMemorySize,
                         SMEM_BYTES);

    dim3 tb(32, 8);
    transpose_kernel<<<dim3(DD / 32, DD / 32, LL), tb>>>(Wq, wqT, DD, DD);
    transpose_kernel<<<dim3(DD / 32, DD / 32, LL), tb>>>(Wk, wkT, DD, DD);
    transpose_kernel<<<dim3(DD / 32, DD / 32, LL), tb>>>(Wv, wvT, DD, DD);
    transpose_kernel<<<dim3(DD / 32, DD / 32, LL), tb>>>(Wo, woT, DD, DD);
    transpose_kernel<<<dim3(FFD / 32, DD / 32, LL), tb>>>(W1, w1T, DD, FFD);
    transpose_kernel<<<dim3(DD / 32, FFD / 32, LL), tb>>>(W2, w2T, FFD, DD);
    transpose_kernel<<<dim3(VV / 32, DD / 32, 1), tb>>>(headW, headT, DD, VV);

    embed_kernel<<<NROWS, 256>>>(idx, tok, pos, x);

    dim3 gDxD(DD / BN, NROWS / BM);          // (4, 32)
    dim3 gDx4D(FFD / BN, NROWS / BM);        // (16, 32)
    dim3 gAttn(TT / 64, BB * HH);            // (16, 64)

    for (int l = 0; l < LL; l++) {
        const __half* wqT_l = wqT + (size_t)l * DD * DD;
        const __half* wkT_l = wkT + (size_t)l * DD * DD;
        const __half* wvT_l = wvT + (size_t)l * DD * DD;
        const __half* woT_l = woT + (size_t)l * DD * DD;
        const __half* w1T_l = w1T + (size_t)l * DD * FFD;
        const __half* w2T_l = w2T + (size_t)l * FFD * DD;

        ln_kernel<<<NROWS, 256>>>(x, ln1g + l * DD, ln1b + l * DD, h);
        tc_gemm<<<gDxD, 256, SMEM_BYTES>>>(h, wqT_l, bq + l * DD, nullptr, q,
                                           NROWS, DD, DD, GF_BIAS | GF_OUTHALF);
        tc_gemm<<<gDxD, 256, SMEM_BYTES>>>(h, wkT_l, bk + l * DD, nullptr, k,
                                           NROWS, DD, DD, GF_BIAS | GF_OUTHALF);
        tc_gemm<<<gDxD, 256, SMEM_BYTES>>>(h, wvT_l, bv + l * DD, nullptr, v,
                                           NROWS, DD, DD, GF_BIAS | GF_OUTHALF);
        fa_kernel<<<gAttn, 128>>>(q, k, v, att);
        tc_gemm<<<gDxD, 256, SMEM_BYTES>>>(att, woT_l, bo + l * DD, x, x,
                                           NROWS, DD, DD, GF_BIAS | GF_RESID);
        ln_kernel<<<NROWS, 256>>>(x, ln2g + l * DD, ln2b + l * DD, h);
        tc_gemm<<<gDx4D, 256, SMEM_BYTES>>>(h, w1T_l, b1 + (size_t)l * FFD,
                                            nullptr, ff, NROWS, FFD, DD,
                                            GF_BIAS | GF_GELU | GF_OUTHALF);
        tc_gemm<<<gDxD, 256, SMEM_BYTES>>>(ff, w2T_l, b2 + l * DD, x, x,
                                           NROWS, DD, FFD, GF_BIAS | GF_RESID);
    }

    ln_kernel<<<NROWS, 256>>>(x, lnfg, lnfb, h);
    dim3 gHead(VV / BN, NROWS / BM);         // (125, 32)
    tc_gemm<<<gHead, 256, SMEM_BYTES>>>(h, headT, nullptr, nullptr, out,
                                        NROWS, VV, DD, 0);
}

// round 6
// speedup vs baseline: 6.3648x; 1.1316x over previous
#include <cuda_runtime.h>
#include <cuda_fp16.h>
#include <math.h>
#include <stdint.h>

// Problem constants
#define BB 4
#define TT 1024
#define VV 32000
#define DD 1024
#define LL 8
#define HH 16
#define NROWS 4096
#define FFD 4096
#define QKVD 3072

// ---------------- scratch (device globals: allocation-free rule) ----------
__device__ float  g_x[NROWS * DD];                 // residual stream (fp32)
__device__ __half g_h[NROWS * DD];
__device__ __half g_qkv[(size_t)NROWS * QKVD];     // fused q|k|v
__device__ __half g_att[NROWS * DD];
__device__ __half g_ff[NROWS * FFD];
__device__ __half g_wqkvT[(size_t)LL * QKVD * DD]; // [3072][1024] per layer
__device__ float  g_bqkv[LL * QKVD];
__device__ __half g_woT[LL * DD * DD];
__device__ __half g_w1T[(size_t)LL * DD * FFD];
__device__ __half g_w2T[(size_t)LL * FFD * DD];
__device__ __half g_headT[(size_t)VV * DD];

// ---------------- PTX helpers ---------------------------------------------
__device__ __forceinline__ uint32_t smem_u32(const void* p) {
    uint32_t a;
    asm("{ .reg .u64 t; cvta.to.shared.u64 t, %1; cvt.u32.u64 %0, t; }"
        : "=r"(a) : "l"(p));
    return a;
}
__device__ __forceinline__ void cp16(uint32_t s, const void* g) {
    asm volatile("cp.async.cg.shared.global [%0], [%1], 16;" :: "r"(s), "l"(g));
}
#define CP_COMMIT() asm volatile("cp.async.commit_group;" ::: "memory")
#define CP_WAIT(n) asm volatile("cp.async.wait_group %0;" :: "n"(n) : "memory")

__device__ __forceinline__ void mma_f16(float* c, const uint32_t* a,
                                        const uint32_t* b) {
    asm volatile(
        "mma.sync.aligned.m16n8k16.row.col.f32.f16.f16.f32 "
        "{%0,%1,%2,%3}, {%4,%5,%6,%7}, {%8,%9}, {%0,%1,%2,%3};"
        : "+f"(c[0]), "+f"(c[1]), "+f"(c[2]), "+f"(c[3])
        : "r"(a[0]), "r"(a[1]), "r"(a[2]), "r"(a[3]), "r"(b[0]), "r"(b[1]));
}
__device__ __forceinline__ void ldsm4(uint32_t* r, uint32_t addr) {
    asm volatile("ldmatrix.sync.aligned.m8n8.x4.shared.b16 {%0,%1,%2,%3}, [%4];"
        : "=r"(r[0]), "=r"(r[1]), "=r"(r[2]), "=r"(r[3]) : "r"(addr));
}

// ---------------- embedding ------------------------------------------------
__global__ void embed_kernel(const int* __restrict__ idx,
                             const float* __restrict__ tok,
                             const float* __restrict__ pos,
                             float* __restrict__ x)
{
    int row = blockIdx.x;
    int t = row % TT;
    int id = idx[row];
    int tid = threadIdx.x;
    const float4* tp = (const float4*)(tok + (size_t)id * DD);
    const float4* pp = (const float4*)(pos + (size_t)t * DD);
    float4 a = tp[tid], b = pp[tid];
    float4 o = make_float4(a.x + b.x, a.y + b.y, a.z + b.z, a.w + b.w);
    ((float4*)(x + (size_t)row * DD))[tid] = o;
}

// ---------------- layernorm: fp32 in, fp16 out -----------------------------
__global__ void ln_kernel(const float* __restrict__ x,
                          const float* __restrict__ g,
                          const float* __restrict__ b,
                          __half* __restrict__ y)
{
    int row = blockIdx.x;
    int tid = threadIdx.x;
    const float4* xr = (const float4*)(x + (size_t)row * DD);
    float4 v = xr[tid];
    float s  = v.x + v.y + v.z + v.w;
    float sq = v.x * v.x + v.y * v.y + v.z * v.z + v.w * v.w;
#pragma unroll
    for (int o = 16; o > 0; o >>= 1) {
        s  += __shfl_xor_sync(0xffffffffu, s, o);
        sq += __shfl_xor_sync(0xffffffffu, sq, o);
    }
    __shared__ float ss[8], ssq[8];
    int wid = tid >> 5;
    if ((tid & 31) == 0) { ss[wid] = s; ssq[wid] = sq; }
    __syncthreads();
    float S = 0.f, SQ = 0.f;
#pragma unroll
    for (int i = 0; i < 8; i++) { S += ss[i]; SQ += ssq[i]; }
    float mean = S * (1.f / DD);
    float var  = SQ * (1.f / DD) - mean * mean;
    float inv  = rsqrtf(var + 1e-5f);
    float4 gv = ((const float4*)g)[tid];
    float4 bv = ((const float4*)b)[tid];
    __half2* yp = (__half2*)(y + (size_t)row * DD);
    yp[tid * 2]     = __floats2half2_rn((v.x - mean) * inv * gv.x + bv.x,
                                        (v.y - mean) * inv * gv.y + bv.y);
    yp[tid * 2 + 1] = __floats2half2_rn((v.z - mean) * inv * gv.z + bv.z,
                                        (v.w - mean) * inv * gv.w + bv.w);
}

// ---------------- weight transpose [K,N] -> fp16 [N,K] ---------------------
__global__ void transpose_kernel(const float* __restrict__ src,
                                 __half* __restrict__ dst, int K, int N,
                                 size_t src_ls, size_t dst_ls, size_t dst_off)
{
    __shared__ float t[32][33];
    const float* s = src + src_ls * blockIdx.z;
    __half* d = dst + dst_ls * blockIdx.z + dst_off;
    int n0 = blockIdx.x * 32, k0 = blockIdx.y * 32;
#pragma unroll
    for (int i = threadIdx.y; i < 32; i += 8)
        t[i][threadIdx.x] = s[(size_t)(k0 + i) * N + n0 + threadIdx.x];
    __syncthreads();
#pragma unroll
    for (int i = threadIdx.y; i < 32; i += 8)
        d[(size_t)(n0 + i) * K + k0 + threadIdx.x] = __float2half_rn(t[threadIdx.x][i]);
}

// ---------------- merge qkv biases -----------------------------------------
__global__ void bias_merge_kernel(const float* __restrict__ bq,
                                  const float* __restrict__ bk,
                                  const float* __restrict__ bv,
                                  float* __restrict__ o)
{
    int l = blockIdx.x;
#pragma unroll
    for (int i = threadIdx.x; i < QKVD; i += 256) {
        float v = (i < DD) ? bq[l * DD + i]
                : (i < 2 * DD) ? bk[l * DD + i - DD]
                : bv[l * DD + i - 2 * DD];
        o[(size_t)l * QKVD + i] = v;
    }
}

// ---------------- fp16 mma.sync GEMM (128x128 tile, 2 CTAs/SM) -------------
#define GF_BIAS    1
#define GF_GELU    2
#define GF_RESID   4
#define GF_OUTHALF 8
#define BM 128
#define BN 128
#define BK 32
#define PADH 40
#define A_STGH (BM * PADH)
#define B_STGH (BN * PADH)
#define STGH   (A_STGH + B_STGH)      // 10240 halves
#define SMEM_BYTES (4 * STGH * 2)     // 81920 B

__global__ void __launch_bounds__(256, 2)
tc_gemm(const __half* __restrict__ A, const __half* __restrict__ Bt,
        const float* __restrict__ bias, const float* __restrict__ resid,
        void* __restrict__ Cout, int M, int N, int K, int flags)
{
    extern __shared__ __half smh[];
    int tid = threadIdx.x;
    int warp = tid >> 5, lane = tid & 31;
    int grp = lane >> 2, tig = lane & 3;
    int row0 = blockIdx.y * BM, col0 = blockIdx.x * BN;
    int NIT = K / BK;
    int m0 = (warp & 1) * 64, n0 = (warp >> 1) * 32;

    uint32_t smb = smem_u32(smh);

    auto load_tile = [&](int slot, int kt) {
        uint32_t ab = smb + slot * (STGH * 2);
        uint32_t bb = ab + A_STGH * 2;
        int k0 = kt * BK;
#pragma unroll
        for (int i = 0; i < 2; i++) {
            int lin = i * 256 + tid;
            int m = lin >> 2, j = lin & 3;
            cp16(ab + (m * PADH + j * 8) * 2,
                 A + (size_t)(row0 + m) * K + k0 + j * 8);
        }
#pragma unroll
        for (int i = 0; i < 2; i++) {
            int lin = i * 256 + tid;
            int n = lin >> 2, j = lin & 3;
            cp16(bb + (n * PADH + j * 8) * 2,
                 Bt + (size_t)(col0 + n) * K + k0 + j * 8);
        }
    };

    float acc[4][4][4];
#pragma unroll
    for (int mt = 0; mt < 4; mt++)
#pragma unroll
        for (int nt = 0; nt < 4; nt++)
#pragma unroll
            for (int r = 0; r < 4; r++) acc[mt][nt][r] = 0.f;

    uint32_t a_off = (uint32_t)(((m0 + (lane & 7) + 8 * ((lane >> 3) & 1)) * PADH
                     + 8 * ((lane >> 4) & 1)) * 2);
    uint32_t b_off = (uint32_t)(A_STGH * 2 +
                     ((n0 + (lane & 7) + 8 * ((lane >> 4) & 1)) * PADH
                     + 8 * ((lane >> 3) & 1)) * 2);

    load_tile(0, 0); CP_COMMIT();
    load_tile(1, 1); CP_COMMIT();
    load_tile(2, 2); CP_COMMIT();

    for (int it = 0; it < NIT; it++) {
        int rem = NIT - 1 - it;
        if (rem >= 2)      CP_WAIT(2);
        else if (rem == 1) CP_WAIT(1);
        else               CP_WAIT(0);
        __syncthreads();
        if (it + 3 < NIT) { load_tile((it + 3) & 3, it + 3); CP_COMMIT(); }

        uint32_t stage = smb + (it & 3) * (STGH * 2);
#pragma unroll
        for (int kk = 0; kk < 2; kk++) {
            uint32_t af[4][4], bq[2][4];
#pragma unroll
            for (int mt = 0; mt < 4; mt++)
                ldsm4(af[mt], stage + a_off + (mt * 16 * PADH + kk * 16) * 2);
#pragma unroll
            for (int nt2 = 0; nt2 < 2; nt2++)
                ldsm4(bq[nt2], stage + b_off + (nt2 * 16 * PADH + kk * 16) * 2);
#pragma unroll
            for (int mt = 0; mt < 4; mt++)
#pragma unroll
                for (int nt = 0; nt < 4; nt++)
                    mma_f16(acc[mt][nt], af[mt], &bq[nt >> 1][(nt & 1) * 2]);
        }
    }

    // ---- epilogue ---------------------------------------------------------
#pragma unroll
    for (int mt = 0; mt < 4; mt++) {
#pragma unroll
        for (int half = 0; half < 2; half++) {
            int r = row0 + m0 + mt * 16 + grp + half * 8;
            const float* rrow = (flags & GF_RESID) ? resid + (size_t)r * N : nullptr;
#pragma unroll
            for (int nt = 0; nt < 4; nt++) {
                int c = col0 + n0 + nt * 8 + 2 * tig;
                float v0 = acc[mt][nt][half * 2 + 0];
                float v1 = acc[mt][nt][half * 2 + 1];
                if (flags & GF_BIAS) { v0 += bias[c]; v1 += bias[c + 1]; }
                if (flags & GF_GELU) {
                    v0 = 0.5f * v0 * (1.f + erff(v0 * 0.70710678118654752f));
                    v1 = 0.5f * v1 * (1.f + erff(v1 * 0.70710678118654752f));
                }
                if (flags & GF_RESID) {
                    float2 rv = *(const float2*)(rrow + c);
                    v0 += rv.x; v1 += rv.y;
                }
                if (flags & GF_OUTHALF) {
                    *(__half2*)((__half*)Cout + (size_t)r * N + c) =
                        __floats2half2_rn(v0, v1);
                } else {
                    *(float2*)((float*)Cout + (size_t)r * N + c) =
                        make_float2(v0, v1);
                }
            }
        }
    }
}

// ---------------- tensor-core flash attention (fused qkv input) ------------
// CTA: 64 queries (4 warps x 16 rows), KV blocks of 64, head dim 64.
__global__ void __launch_bounds__(128, 1) fa_kernel(
    const __half* __restrict__ QKV, __half* __restrict__ O)
{
    __shared__ __half Qs[64][72];
    __shared__ __half Ks[64][72];
    __shared__ __half Vt[64][72];     // V transposed: [dim][key]

    int tid = threadIdx.x;
    int warp = tid >> 5, lane = tid & 31;
    int grp = lane >> 2, tig = lane & 3;
    int bh = blockIdx.y;
    int b = bh >> 4, h = bh & 15;
    int q0 = blockIdx.x * 64;

    size_t bq_ = ((size_t)b * TT) * QKVD + (size_t)h * 64;          // Q cols
    size_t bk_ = bq_ + DD;
    size_t bv_ = bq_ + 2 * DD;
    size_t bo_ = ((size_t)b * TT) * DD + (size_t)h * 64;

    const __half2 sc2 = __floats2half2_rn(0.125f, 0.125f);
    for (int i = tid; i < 64 * 8; i += 128) {
        int row = i >> 3, c8 = (i & 7) * 8;
        uint4 u = *(const uint4*)(QKV + bq_ + (size_t)(q0 + row) * QKVD + c8);
        __half2* hp = (__half2*)&u;
#pragma unroll
        for (int j = 0; j < 4; j++) hp[j] = __hmul2(hp[j], sc2);
        *(uint4*)&Qs[row][c8] = u;
    }
    __syncthreads();

    uint32_t aq[4][4];
    int mrow = warp * 16;
#pragma unroll
    for (int s = 0; s < 4; s++) {
        aq[s][0] = *(const uint32_t*)&Qs[mrow + grp][16 * s + 2 * tig];
        aq[s][1] = *(const uint32_t*)&Qs[mrow + grp + 8][16 * s + 2 * tig];
        aq[s][2] = *(const uint32_t*)&Qs[mrow + grp][16 * s + 2 * tig + 8];
        aq[s][3] = *(const uint32_t*)&Qs[mrow + grp + 8][16 * s + 2 * tig + 8];
    }

    float o[8][4];
#pragma unroll
    for (int d = 0; d < 8; d++)
#pragma unroll
        for (int r = 0; r < 4; r++) o[d][r] = 0.f;
    float m0v = -1e30f, m1v = -1e30f, l0 = 0.f, l1 = 0.f;

    for (int kt0 = 0; kt0 <= q0; kt0 += 64) {
        __syncthreads();
        for (int i = tid; i < 64 * 8; i += 128) {
            int row = i >> 3, c8 = (i & 7) * 8;
            *(uint4*)&Ks[row][c8] =
                *(const uint4*)(QKV + bk_ + (size_t)(kt0 + row) * QKVD + c8);
        }
        for (int i = tid; i < 64 * 32; i += 128) {
            int row = i & 63, cp = i >> 6;
            __half2 v = *(const __half2*)(QKV + bv_ + (size_t)(kt0 + row) * QKVD + cp * 2);
            Vt[cp * 2][row] = __low2half(v);
            Vt[cp * 2 + 1][row] = __high2half(v);
        }
        __syncthreads();

        float sc[8][4];
#pragma unroll
        for (int j = 0; j < 8; j++)
#pragma unroll
            for (int r = 0; r < 4; r++) sc[j][r] = 0.f;
#pragma unroll
        for (int s = 0; s < 4; s++) {
#pragma unroll
            for (int j = 0; j < 8; j++) {
                uint32_t bf[2];
                bf[0] = *(const uint32_t*)&Ks[8 * j + grp][16 * s + 2 * tig];
                bf[1] = *(const uint32_t*)&Ks[8 * j + grp][16 * s + 2 * tig + 8];
                mma_f16(sc[j], aq[s], bf);
            }
        }

        if (kt0 == q0) {
            int lq0 = mrow + grp, lq1 = mrow + grp + 8;
#pragma unroll
            for (int j = 0; j < 8; j++) {
                int lk = 8 * j + 2 * tig;
                if (lk > lq0)     sc[j][0] = -1e30f;
                if (lk + 1 > lq0) sc[j][1] = -1e30f;
                if (lk > lq1)     sc[j][2] = -1e30f;
                if (lk + 1 > lq1) sc[j][3] = -1e30f;
            }
        }

        float mx0 = -1e30f, mx1 = -1e30f;
#pragma unroll
        for (int j = 0; j < 8; j++) {
            mx0 = fmaxf(mx0, fmaxf(sc[j][0], sc[j][1]));
            mx1 = fmaxf(mx1, fmaxf(sc[j][2], sc[j][3]));
        }
        mx0 = fmaxf(mx0, __shfl_xor_sync(0xffffffffu, mx0, 1));
        mx0 = fmaxf(mx0, __shfl_xor_sync(0xffffffffu, mx0, 2));
        mx1 = fmaxf(mx1, __shfl_xor_sync(0xffffffffu, mx1, 1));
        mx1 = fmaxf(mx1, __shfl_xor_sync(0xffffffffu, mx1, 2));

        float mn0 = fmaxf(m0v, mx0), mn1 = fmaxf(m1v, mx1);
        float cr0 = __expf(m0v - mn0), cr1 = __expf(m1v - mn1);
        m0v = mn0; m1v = mn1;

        uint32_t ap[4][4];
        float rs0 = 0.f, rs1 = 0.f;
#pragma unroll
        for (int j = 0; j < 8; j++) {
            float p0 = __expf(sc[j][0] - mn0);
            float p1 = __expf(sc[j][1] - mn0);
            float p2 = __expf(sc[j][2] - mn1);
            float p3 = __expf(sc[j][3] - mn1);
            rs0 += p0 + p1; rs1 += p2 + p3;
            int s = j >> 1, odd = j & 1;
            __half2 h01 = __floats2half2_rn(p0, p1);
            __half2 h23 = __floats2half2_rn(p2, p3);
            ap[s][odd * 2 + 0] = *(uint32_t*)&h01;
            ap[s][odd * 2 + 1] = *(uint32_t*)&h23;
        }
        rs0 += __shfl_xor_sync(0xffffffffu, rs0, 1);
        rs0 += __shfl_xor_sync(0xffffffffu, rs0, 2);
        rs1 += __shfl_xor_sync(0xffffffffu, rs1, 1);
        rs1 += __shfl_xor_sync(0xffffffffu, rs1, 2);
        l0 = l0 * cr0 + rs0;
        l1 = l1 * cr1 + rs1;

#pragma unroll
        for (int d = 0; d < 8; d++) {
            o[d][0] *= cr0; o[d][1] *= cr0;
            o[d][2] *= cr1; o[d][3] *= cr1;
        }

#pragma unroll
        for (int s = 0; s < 4; s++) {
#pragma unroll
            for (int d = 0; d < 8; d++) {
                uint32_t bf[2];
                bf[0] = *(const uint32_t*)&Vt[8 * d + grp][16 * s + 2 * tig];
                bf[1] = *(const uint32_t*)&Vt[8 * d + grp][16 * s + 2 * tig + 8];
                mma_f16(o[d], ap[s], bf);
            }
        }
    }

    float i0 = 1.f / l0, i1 = 1.f / l1;
    int r0 = q0 + mrow + grp, r1 = r0 + 8;
#pragma unroll
    for (int d = 0; d < 8; d++) {
        int c = 8 * d + 2 * tig;
        *(__half2*)(O + bo_ + (size_t)r0 * DD + c) =
            __floats2half2_rn(o[d][0] * i0, o[d][1] * i0);
        *(__half2*)(O + bo_ + (size_t)r1 * DD + c) =
            __floats2half2_rn(o[d][2] * i1, o[d][3] * i1);
    }
}

// ---------------- host orchestration ---------------------------------------
extern "C" void kernel_launch(void* const* d_in, const int* in_sizes, int n_in,
                              void* d_out, int out_size)
{
    const int*   idx    = (const int*)  d_in[0];
    const float* tok    = (const float*)d_in[1];
    const float* pos    = (const float*)d_in[2];
    const float* ln1g   = (const float*)d_in[3];
    const float* ln1b   = (const float*)d_in[4];
    const float* Wq     = (const float*)d_in[5];
    const float* bq     = (const float*)d_in[6];
    const float* Wk     = (const float*)d_in[7];
    const float* bk     = (const float*)d_in[8];
    const float* Wv     = (const float*)d_in[9];
    const float* bv     = (const float*)d_in[10];
    const float* Wo     = (const float*)d_in[11];
    const float* bo     = (const float*)d_in[12];
    const float* ln2g   = (const float*)d_in[13];
    const float* ln2b   = (const float*)d_in[14];
    const float* W1     = (const float*)d_in[15];
    const float* b1     = (const float*)d_in[16];
    const float* W2     = (const float*)d_in[17];
    const float* b2     = (const float*)d_in[18];
    const float* lnfg   = (const float*)d_in[19];
    const float* lnfb   = (const float*)d_in[20];
    const float* headW  = (const float*)d_in[21];
    float* out = (float*)d_out;

    float *x, *bqkv;
    __half *h, *qkv, *att, *ff;
    __half *wqkvT, *woT, *w1T, *w2T, *headT;
    cudaGetSymbolAddress((void**)&x,    g_x);
    cudaGetSymbolAddress((void**)&h,    g_h);
    cudaGetSymbolAddress((void**)&qkv,  g_qkv);
    cudaGetSymbolAddress((void**)&att,  g_att);
    cudaGetSymbolAddress((void**)&ff,   g_ff);
    cudaGetSymbolAddress((void**)&bqkv, g_bqkv);
    cudaGetSymbolAddress((void**)&wqkvT, g_wqkvT);
    cudaGetSymbolAddress((void**)&woT,  g_woT);
    cudaGetSymbolAddress((void**)&w1T,  g_w1T);
    cudaGetSymbolAddress((void**)&w2T,  g_w2T);
    cudaGetSymbolAddress((void**)&headT, g_headT);

    cudaFuncSetAttribute(tc_gemm, cudaFuncAttributeMaxDynamicSharedMemorySize,
                         SMEM_BYTES);

    dim3 tb(32, 8);
    size_t DxD = (size_t)DD * DD;
    // QKV weights -> one [3072][1024] matrix per layer
    transpose_kernel<<<dim3(DD / 32, DD / 32, LL), tb>>>(
        Wq, wqkvT, DD, DD, DxD, 3 * DxD, 0);
    transpose_kernel<<<dim3(DD / 32, DD / 32, LL), tb>>>(
        Wk, wqkvT, DD, DD, DxD, 3 * DxD, DxD);
    transpose_kernel<<<dim3(DD / 32, DD / 32, LL), tb>>>(
        Wv, wqkvT, DD, DD, DxD, 3 * DxD, 2 * DxD);
    transpose_kernel<<<dim3(DD / 32, DD / 32, LL), tb>>>(
        Wo, woT, DD, DD, DxD, DxD, 0);
    transpose_kernel<<<dim3(FFD / 32, DD / 32, LL), tb>>>(
        W1, w1T, DD, FFD, (size_t)DD * FFD, (size_t)DD * FFD, 0);
    transpose_kernel<<<dim3(DD / 32, FFD / 32, LL), tb>>>(
        W2, w2T, FFD, DD, (size_t)DD * FFD, (size_t)DD * FFD, 0);
    transpose_kernel<<<dim3(VV / 32, DD / 32, 1), tb>>>(
        headW, headT, DD, VV, 0, 0, 0);
    bias_merge_kernel<<<LL, 256>>>(bq, bk, bv, bqkv);

    embed_kernel<<<NROWS, 256>>>(idx, tok, pos, x);

    dim3 gQKV(QKVD / BN, NROWS / BM);        // (24, 32)
    dim3 gDxD(DD / BN, NROWS / BM);          // (8, 32)
    dim3 gDx4D(FFD / BN, NROWS / BM);        // (32, 32)
    dim3 gAttn(TT / 64, BB * HH);            // (16, 64)

    for (int l = 0; l < LL; l++) {
        const __half* wqkvT_l = wqkvT + (size_t)l * 3 * DxD;
        const __half* woT_l = woT + (size_t)l * DxD;
        const __half* w1T_l = w1T + (size_t)l * DD * FFD;
        const __half* w2T_l = w2T + (size_t)l * DD * FFD;

        ln_kernel<<<NROWS, 256>>>(x, ln1g + l * DD, ln1b + l * DD, h);
        tc_gemm<<<gQKV, 256, SMEM_BYTES>>>(h, wqkvT_l, bqkv + (size_t)l * QKVD,
                                           nullptr, qkv, NROWS, QKVD, DD,
                                           GF_BIAS | GF_OUTHALF);
        fa_kernel<<<gAttn, 128>>>(qkv, att);
        tc_gemm<<<gDxD, 256, SMEM_BYTES>>>(att, woT_l, bo + l * DD, x, x,
                                           NROWS, DD, DD, GF_BIAS | GF_RESID);
        ln_kernel<<<NROWS, 256>>>(x, ln2g + l * DD, ln2b + l * DD, h);
        tc_gemm<<<gDx4D, 256, SMEM_BYTES>>>(h, w1T_l, b1 + (size_t)l * FFD,
                                            nullptr, ff, NROWS, FFD, DD,
                                            GF_BIAS | GF_GELU | GF_OUTHALF);
        tc_gemm<<<gDxD, 256, SMEM_BYTES>>>(ff, w2T_l, b2 + l * DD, x, x,
                                           NROWS, DD, FFD, GF_BIAS | GF_RESID);
    }

    ln_kernel<<<NROWS, 256>>>(x, lnfg, lnfb, h);
    dim3 gHead(VV / BN, NROWS / BM);         // (250, 32)
    tc_gemm<<<gHead, 256, SMEM_BYTES>>>(h, headT, nullptr, nullptr, out,
                                        NROWS, VV, DD, 0);
}

// round 7
// speedup vs baseline: 6.7847x; 1.0660x over previous
#include <cuda_runtime.h>
#include <cuda_fp16.h>
#include <math.h>
#include <stdint.h>

// Problem constants
#define BB 4
#define TT 1024
#define VV 32000
#define DD 1024
#define LL 8
#define HH 16
#define NROWS 4096
#define FFD 4096
#define QKVD 3072

// ---------------- scratch (device globals: allocation-free rule) ----------
__device__ float  g_x[NROWS * DD];                 // residual stream (fp32)
__device__ __half g_h[NROWS * DD];
__device__ __half g_qkv[(size_t)NROWS * QKVD];     // fused q|k|v
__device__ __half g_att[NROWS * DD];
__device__ __half g_ff[NROWS * FFD];
__device__ __half g_wqkv[(size_t)LL * DD * QKVD];  // [K=1024][N=3072] per layer
__device__ float  g_bqkv[LL * QKVD];
__device__ __half g_wo[LL * DD * DD];              // [K][N] row-major fp16
__device__ __half g_w1[(size_t)LL * DD * FFD];
__device__ __half g_w2[(size_t)LL * FFD * DD];
__device__ __half g_head[(size_t)DD * VV];

// ---------------- PTX helpers ---------------------------------------------
__device__ __forceinline__ uint32_t smem_u32(const void* p) {
    uint32_t a;
    asm("{ .reg .u64 t; cvta.to.shared.u64 t, %1; cvt.u32.u64 %0, t; }"
        : "=r"(a) : "l"(p));
    return a;
}
__device__ __forceinline__ void cp16(uint32_t s, const void* g) {
    asm volatile("cp.async.cg.shared.global [%0], [%1], 16;" :: "r"(s), "l"(g));
}
#define CP_COMMIT() asm volatile("cp.async.commit_group;" ::: "memory")
#define CP_WAIT(n) asm volatile("cp.async.wait_group %0;" :: "n"(n) : "memory")

__device__ __forceinline__ void mma_f16(float* c, const uint32_t* a,
                                        const uint32_t* b) {
    asm volatile(
        "mma.sync.aligned.m16n8k16.row.col.f32.f16.f16.f32 "
        "{%0,%1,%2,%3}, {%4,%5,%6,%7}, {%8,%9}, {%0,%1,%2,%3};"
        : "+f"(c[0]), "+f"(c[1]), "+f"(c[2]), "+f"(c[3])
        : "r"(a[0]), "r"(a[1]), "r"(a[2]), "r"(a[3]), "r"(b[0]), "r"(b[1]));
}
__device__ __forceinline__ void ldsm4(uint32_t* r, uint32_t addr) {
    asm volatile("ldmatrix.sync.aligned.m8n8.x4.shared.b16 {%0,%1,%2,%3}, [%4];"
        : "=r"(r[0]), "=r"(r[1]), "=r"(r[2]), "=r"(r[3]) : "r"(addr));
}
__device__ __forceinline__ void ldsm4t(uint32_t* r, uint32_t addr) {
    asm volatile("ldmatrix.sync.aligned.m8n8.x4.trans.shared.b16 {%0,%1,%2,%3}, [%4];"
        : "=r"(r[0]), "=r"(r[1]), "=r"(r[2]), "=r"(r[3]) : "r"(addr));
}
__device__ __forceinline__ void st_half4(__half* p, float4 v) {
    __half2 a = __floats2half2_rn(v.x, v.y);
    __half2 b = __floats2half2_rn(v.z, v.w);
    uint2 u;
    u.x = *(uint32_t*)&a; u.y = *(uint32_t*)&b;
    *(uint2*)p = u;
}

// ---------------- fused weight prep (cast + qkv/bias merge) ----------------
// grid: (32768, 6), block 256, 4 elems/thread
__global__ void prep_kernel(const float* __restrict__ Wq, const float* __restrict__ Wk,
                            const float* __restrict__ Wv, const float* __restrict__ Wo,
                            const float* __restrict__ W1, const float* __restrict__ W2,
                            const float* __restrict__ Hd,
                            const float* __restrict__ bq, const float* __restrict__ bk,
                            const float* __restrict__ bv,
                            __half* __restrict__ wqkv, __half* __restrict__ wo,
                            __half* __restrict__ w1, __half* __restrict__ w2,
                            __half* __restrict__ hd, float* __restrict__ bqkv)
{
    size_t base = ((size_t)blockIdx.x * 256 + threadIdx.x) * 4;
    switch (blockIdx.y) {
    case 0: {   // merged qkv weight: [l][k][n<3072]
        if (base >= (size_t)LL * DD * QKVD) return;
        size_t n = base % QKVD, lk = base / QKVD;
        const float* s = (n < DD) ? Wq : (n < 2 * DD) ? Wk : Wv;
        size_t nn = n & (DD - 1);
        st_half4(wqkv + base, *(const float4*)(s + lk * DD + nn));
        break; }
    case 1: {
        if (base >= (size_t)LL * DD * DD) return;
        st_half4(wo + base, *(const float4*)(Wo + base));
        break; }
    case 2: {
        if (base >= (size_t)LL * DD * FFD) return;
        st_half4(w1 + base, *(const float4*)(W1 + base));
        break; }
    case 3: {
        if (base >= (size_t)LL * FFD * DD) return;
        st_half4(w2 + base, *(const float4*)(W2 + base));
        break; }
    case 4: {
        if (base >= (size_t)DD * VV) return;
        st_half4(hd + base, *(const float4*)(Hd + base));
        break; }
    default: {  // merged qkv bias (fp32)
        if (base >= (size_t)LL * QKVD) return;
        size_t n = base % QKVD, l = base / QKVD;
        const float* s = (n < DD) ? bq : (n < 2 * DD) ? bk : bv;
        *(float4*)(bqkv + base) = *(const float4*)(s + l * DD + (n & (DD - 1)));
        break; }
    }
}

// ---------------- embedding ------------------------------------------------
__global__ void embed_kernel(const int* __restrict__ idx,
                             const float* __restrict__ tok,
                             const float* __restrict__ pos,
                             float* __restrict__ x)
{
    int row = blockIdx.x;
    int t = row % TT;
    int id = idx[row];
    int tid = threadIdx.x;
    const float4* tp = (const float4*)(tok + (size_t)id * DD);
    const float4* pp = (const float4*)(pos + (size_t)t * DD);
    float4 a = tp[tid], b = pp[tid];
    ((float4*)(x + (size_t)row * DD))[tid] =
        make_float4(a.x + b.x, a.y + b.y, a.z + b.z, a.w + b.w);
}

// ---------------- layernorm: warp-per-row, fp32 in / fp16 out --------------
// grid 512, block 256 (8 rows per block)
__global__ void ln_kernel(const float* __restrict__ x,
                          const float* __restrict__ g,
                          const float* __restrict__ b,
                          __half* __restrict__ y)
{
    int lane = threadIdx.x & 31, warp = threadIdx.x >> 5;
    int row = blockIdx.x * 8 + warp;
    const float4* xr = (const float4*)(x + (size_t)row * DD);
    float4 v[8];
    float s = 0.f, sq = 0.f;
#pragma unroll
    for (int i = 0; i < 8; i++) {
        v[i] = xr[i * 32 + lane];
        s  += v[i].x + v[i].y + v[i].z + v[i].w;
        sq += v[i].x * v[i].x + v[i].y * v[i].y + v[i].z * v[i].z + v[i].w * v[i].w;
    }
#pragma unroll
    for (int o = 16; o > 0; o >>= 1) {
        s  += __shfl_xor_sync(0xffffffffu, s, o);
        sq += __shfl_xor_sync(0xffffffffu, sq, o);
    }
    float mean = s * (1.f / DD);
    float var  = sq * (1.f / DD) - mean * mean;
    float inv  = rsqrtf(var + 1e-5f);
    const float4* gr = (const float4*)g;
    const float4* br = (const float4*)b;
    __half* yrow = y + (size_t)row * DD;
#pragma unroll
    for (int i = 0; i < 8; i++) {
        float4 gv = gr[i * 32 + lane], bv = br[i * 32 + lane];
        float4 o;
        o.x = (v[i].x - mean) * inv * gv.x + bv.x;
        o.y = (v[i].y - mean) * inv * gv.y + bv.y;
        o.z = (v[i].z - mean) * inv * gv.z + bv.z;
        o.w = (v[i].w - mean) * inv * gv.w + bv.w;
        st_half4(yrow + (i * 32 + lane) * 4, o);
    }
}

// ---------------- fp16 mma.sync GEMM (B row-major via ldmatrix.trans) ------
// C[M,N] = A[M,K] @ B[K,N]. CTA 128x128, 8 warps, warp tile 64x32.
#define GF_BIAS    1
#define GF_GELU    2
#define GF_RESID   4
#define GF_OUTHALF 8
#define BM 128
#define BN 128
#define BK 32
#define PADH 40                        // A row pad (halves)
#define PADB 136                       // B row pad (halves)
#define A_STGH (BM * PADH)             // 5120
#define B_STGH (BK * PADB)             // 4352
#define STGH   (A_STGH + B_STGH)       // 9472 halves = 18944 B
#define NST 5
#define SMEM_BYTES (NST * STGH * 2)    // 94720 B

__global__ void __launch_bounds__(256, 2)
tc_gemm(const __half* __restrict__ A, const __half* __restrict__ B,
        const float* __restrict__ bias, const float* __restrict__ resid,
        void* __restrict__ Cout, int M, int N, int K, int flags)
{
    extern __shared__ __half smh[];
    int tid = threadIdx.x;
    int warp = tid >> 5, lane = tid & 31;
    int grp = lane >> 2, tig = lane & 3;
    int row0 = blockIdx.y * BM, col0 = blockIdx.x * BN;
    int NIT = K / BK;
    int m0 = (warp & 1) * 64, n0 = (warp >> 1) * 32;

    uint32_t smb = smem_u32(smh);

    auto load_tile = [&](int slot, int kt) {
        uint32_t ab = smb + slot * (STGH * 2);
        uint32_t bb = ab + A_STGH * 2;
        int k0 = kt * BK;
#pragma unroll
        for (int i = 0; i < 2; i++) {          // A: 512 chunks of 8 halves
            int lin = i * 256 + tid;
            int m = lin >> 2, j = lin & 3;
            cp16(ab + (m * PADH + j * 8) * 2,
                 A + (size_t)(row0 + m) * K + k0 + j * 8);
        }
#pragma unroll
        for (int i = 0; i < 2; i++) {          // B: 512 chunks ([BK][BN])
            int lin = i * 256 + tid;
            int kr = lin >> 4, nc = lin & 15;
            cp16(bb + (kr * PADB + nc * 8) * 2,
                 B + (size_t)(k0 + kr) * N + col0 + nc * 8);
        }
    };

    float acc[4][4][4];
#pragma unroll
    for (int mt = 0; mt < 4; mt++)
#pragma unroll
        for (int nt = 0; nt < 4; nt++)
#pragma unroll
            for (int r = 0; r < 4; r++) acc[mt][nt][r] = 0.f;

    uint32_t a_off = (uint32_t)(((m0 + (lane & 7) + 8 * ((lane >> 3) & 1)) * PADH
                     + 8 * ((lane >> 4) & 1)) * 2);
    // B trans: lane addr = row (k0 + (lane&7) + 8*bit3), col (n0 + 8*bit4)
    uint32_t b_off = (uint32_t)(A_STGH * 2 +
                     (((lane & 7) + 8 * ((lane >> 3) & 1)) * PADB
                     + n0 + 8 * ((lane >> 4) & 1)) * 2);

    load_tile(0, 0); CP_COMMIT();
    load_tile(1, 1); CP_COMMIT();
    load_tile(2, 2); CP_COMMIT();
    load_tile(3, 3); CP_COMMIT();

    int slot = 0;
    for (int it = 0; it < NIT; it++) {
        int rem = NIT - 1 - it;
        if (rem >= 3)      CP_WAIT(3);
        else if (rem == 2) CP_WAIT(2);
        else if (rem == 1) CP_WAIT(1);
        else               CP_WAIT(0);
        __syncthreads();
        if (it + 4 < NIT) {
            int ns = slot + 4; if (ns >= NST) ns -= NST;
            load_tile(ns, it + 4); CP_COMMIT();
        }

        uint32_t stage = smb + slot * (STGH * 2);
#pragma unroll
        for (int kk = 0; kk < 2; kk++) {
            uint32_t af[4][4], bq[2][4];
#pragma unroll
            for (int mt = 0; mt < 4; mt++)
                ldsm4(af[mt], stage + a_off + (mt * 16 * PADH + kk * 16) * 2);
#pragma unroll
            for (int nt2 = 0; nt2 < 2; nt2++)
                ldsm4t(bq[nt2], stage + b_off + (kk * 16 * PADB + nt2 * 16) * 2);
#pragma unroll
            for (int mt = 0; mt < 4; mt++)
#pragma unroll
                for (int nt = 0; nt < 4; nt++)
                    mma_f16(acc[mt][nt], af[mt], &bq[nt >> 1][(nt & 1) * 2]);
        }
        if (++slot >= NST) slot = 0;
    }

    // ---- epilogue ---------------------------------------------------------
#pragma unroll
    for (int mt = 0; mt < 4; mt++) {
#pragma unroll
        for (int half = 0; half < 2; half++) {
            int r = row0 + m0 + mt * 16 + grp + half * 8;
            const float* rrow = (flags & GF_RESID) ? resid + (size_t)r * N : nullptr;
#pragma unroll
            for (int nt = 0; nt < 4; nt++) {
                int c = col0 + n0 + nt * 8 + 2 * tig;
                float v0 = acc[mt][nt][half * 2 + 0];
                float v1 = acc[mt][nt][half * 2 + 1];
                if (flags & GF_BIAS) { v0 += bias[c]; v1 += bias[c + 1]; }
                if (flags & GF_GELU) {
                    v0 = 0.5f * v0 * (1.f + erff(v0 * 0.70710678118654752f));
                    v1 = 0.5f * v1 * (1.f + erff(v1 * 0.70710678118654752f));
                }
                if (flags & GF_RESID) {
                    float2 rv = *(const float2*)(rrow + c);
                    v0 += rv.x; v1 += rv.y;
                }
                if (flags & GF_OUTHALF) {
                    *(__half2*)((__half*)Cout + (size_t)r * N + c) =
                        __floats2half2_rn(v0, v1);
                } else {
                    *(float2*)((float*)Cout + (size_t)r * N + c) =
                        make_float2(v0, v1);
                }
            }
        }
    }
}

// ---------------- tensor-core flash attention (fused qkv input) ------------
__global__ void __launch_bounds__(128, 1) fa_kernel(
    const __half* __restrict__ QKV, __half* __restrict__ O)
{
    __shared__ __half Qs[64][72];
    __shared__ __half Ks[64][72];
    __shared__ __half Vt[64][72];

    int tid = threadIdx.x;
    int warp = tid >> 5, lane = tid & 31;
    int grp = lane >> 2, tig = lane & 3;
    int bh = blockIdx.y;
    int b = bh >> 4, h = bh & 15;
    int q0 = blockIdx.x * 64;

    size_t bq_ = ((size_t)b * TT) * QKVD + (size_t)h * 64;
    size_t bk_ = bq_ + DD;
    size_t bv_ = bq_ + 2 * DD;
    size_t bo_ = ((size_t)b * TT) * DD + (size_t)h * 64;

    const __half2 sc2 = __floats2half2_rn(0.125f, 0.125f);
    for (int i = tid; i < 64 * 8; i += 128) {
        int row = i >> 3, c8 = (i & 7) * 8;
        uint4 u = *(const uint4*)(QKV + bq_ + (size_t)(q0 + row) * QKVD + c8);
        __half2* hp = (__half2*)&u;
#pragma unroll
        for (int j = 0; j < 4; j++) hp[j] = __hmul2(hp[j], sc2);
        *(uint4*)&Qs[row][c8] = u;
    }
    __syncthreads();

    uint32_t aq[4][4];
    int mrow = warp * 16;
#pragma unroll
    for (int s = 0; s < 4; s++) {
        aq[s][0] = *(const uint32_t*)&Qs[mrow + grp][16 * s + 2 * tig];
        aq[s][1] = *(const uint32_t*)&Qs[mrow + grp + 8][16 * s + 2 * tig];
        aq[s][2] = *(const uint32_t*)&Qs[mrow + grp][16 * s + 2 * tig + 8];
        aq[s][3] = *(const uint32_t*)&Qs[mrow + grp + 8][16 * s + 2 * tig + 8];
    }

    float o[8][4];
#pragma unroll
    for (int d = 0; d < 8; d++)
#pragma unroll
        for (int r = 0; r < 4; r++) o[d][r] = 0.f;
    float m0v = -1e30f, m1v = -1e30f, l0 = 0.f, l1 = 0.f;

    for (int kt0 = 0; kt0 <= q0; kt0 += 64) {
        __syncthreads();
        for (int i = tid; i < 64 * 8; i += 128) {
            int row = i >> 3, c8 = (i & 7) * 8;
            *(uint4*)&Ks[row][c8] =
                *(const uint4*)(QKV + bk_ + (size_t)(kt0 + row) * QKVD + c8);
        }
        for (int i = tid; i < 64 * 32; i += 128) {
            int row = i & 63, cp = i >> 6;
            __half2 v = *(const __half2*)(QKV + bv_ + (size_t)(kt0 + row) * QKVD + cp * 2);
            Vt[cp * 2][row] = __low2half(v);
            Vt[cp * 2 + 1][row] = __high2half(v);
        }
        __syncthreads();

        float sc[8][4];
#pragma unroll
        for (int j = 0; j < 8; j++)
#pragma unroll
            for (int r = 0; r < 4; r++) sc[j][r] = 0.f;
#pragma unroll
        for (int s = 0; s < 4; s++) {
#pragma unroll
            for (int j = 0; j < 8; j++) {
                uint32_t bf[2];
                bf[0] = *(const uint32_t*)&Ks[8 * j + grp][16 * s + 2 * tig];
                bf[1] = *(const uint32_t*)&Ks[8 * j + grp][16 * s + 2 * tig + 8];
                mma_f16(sc[j], aq[s], bf);
            }
        }

        if (kt0 == q0) {
            int lq0 = mrow + grp, lq1 = mrow + grp + 8;
#pragma unroll
            for (int j = 0; j < 8; j++) {
                int lk = 8 * j + 2 * tig;
                if (lk > lq0)     sc[j][0] = -1e30f;
                if (lk + 1 > lq0) sc[j][1] = -1e30f;
                if (lk > lq1)     sc[j][2] = -1e30f;
                if (lk + 1 > lq1) sc[j][3] = -1e30f;
            }
        }

        float mx0 = -1e30f, mx1 = -1e30f;
#pragma unroll
        for (int j = 0; j < 8; j++) {
            mx0 = fmaxf(mx0, fmaxf(sc[j][0], sc[j][1]));
            mx1 = fmaxf(mx1, fmaxf(sc[j][2], sc[j][3]));
        }
        mx0 = fmaxf(mx0, __shfl_xor_sync(0xffffffffu, mx0, 1));
        mx0 = fmaxf(mx0, __shfl_xor_sync(0xffffffffu, mx0, 2));
        mx1 = fmaxf(mx1, __shfl_xor_sync(0xffffffffu, mx1, 1));
        mx1 = fmaxf(mx1, __shfl_xor_sync(0xffffffffu, mx1, 2));

        float mn0 = fmaxf(m0v, mx0), mn1 = fmaxf(m1v, mx1);
        float cr0 = __expf(m0v - mn0), cr1 = __expf(m1v - mn1);
        m0v = mn0; m1v = mn1;

        uint32_t ap[4][4];
        float rs0 = 0.f, rs1 = 0.f;
#pragma unroll
        for (int j = 0; j < 8; j++) {
            float p0 = __expf(sc[j][0] - mn0);
            float p1 = __expf(sc[j][1] - mn0);
            float p2 = __expf(sc[j][2] - mn1);
            float p3 = __expf(sc[j][3] - mn1);
            rs0 += p0 + p1; rs1 += p2 + p3;
            int s = j >> 1, odd = j & 1;
            __half2 h01 = __floats2half2_rn(p0, p1);
            __half2 h23 = __floats2half2_rn(p2, p3);
            ap[s][odd * 2 + 0] = *(uint32_t*)&h01;
            ap[s][odd * 2 + 1] = *(uint32_t*)&h23;
        }
        rs0 += __shfl_xor_sync(0xffffffffu, rs0, 1);
        rs0 += __shfl_xor_sync(0xffffffffu, rs0, 2);
        rs1 += __shfl_xor_sync(0xffffffffu, rs1, 1);
        rs1 += __shfl_xor_sync(0xffffffffu, rs1, 2);
        l0 = l0 * cr0 + rs0;
        l1 = l1 * cr1 + rs1;

#pragma unroll
        for (int d = 0; d < 8; d++) {
            o[d][0] *= cr0; o[d][1] *= cr0;
            o[d][2] *= cr1; o[d][3] *= cr1;
        }

#pragma unroll
        for (int s = 0; s < 4; s++) {
#pragma unroll
            for (int d = 0; d < 8; d++) {
                uint32_t bf[2];
                bf[0] = *(const uint32_t*)&Vt[8 * d + grp][16 * s + 2 * tig];
                bf[1] = *(const uint32_t*)&Vt[8 * d + grp][16 * s + 2 * tig + 8];
                mma_f16(o[d], ap[s], bf);
            }
        }
    }

    float i0 = 1.f / l0, i1 = 1.f / l1;
    int r0 = q0 + mrow + grp, r1 = r0 + 8;
#pragma unroll
    for (int d = 0; d < 8; d++) {
        int c = 8 * d + 2 * tig;
        *(__half2*)(O + bo_ + (size_t)r0 * DD + c) =
            __floats2half2_rn(o[d][0] * i0, o[d][1] * i0);
        *(__half2*)(O + bo_ + (size_t)r1 * DD + c) =
            __floats2half2_rn(o[d][2] * i1, o[d][3] * i1);
    }
}

// ---------------- host orchestration ---------------------------------------
extern "C" void kernel_launch(void* const* d_in, const int* in_sizes, int n_in,
                              void* d_out, int out_size)
{
    const int*   idx    = (const int*)  d_in[0];
    const float* tok    = (const float*)d_in[1];
    const float* pos    = (const float*)d_in[2];
    const float* ln1g   = (const float*)d_in[3];
    const float* ln1b   = (const float*)d_in[4];
    const float* Wq     = (const float*)d_in[5];
    const float* bq     = (const float*)d_in[6];
    const float* Wk     = (const float*)d_in[7];
    const float* bk     = (const float*)d_in[8];
    const float* Wv     = (const float*)d_in[9];
    const float* bv     = (const float*)d_in[10];
    const float* Wo     = (const float*)d_in[11];
    const float* bo     = (const float*)d_in[12];
    const float* ln2g   = (const float*)d_in[13];
    const float* ln2b   = (const float*)d_in[14];
    const float* W1     = (const float*)d_in[15];
    const float* b1     = (const float*)d_in[16];
    const float* W2     = (const float*)d_in[17];
    const float* b2     = (const float*)d_in[18];
    const float* lnfg   = (const float*)d_in[19];
    const float* lnfb   = (const float*)d_in[20];
    const float* headW  = (const float*)d_in[21];
    float* out = (float*)d_out;

    float *x, *bqkv;
    __half *h, *qkv, *att, *ff;
    __half *wqkv, *wo, *w1, *w2, *head;
    cudaGetSymbolAddress((void**)&x,    g_x);
    cudaGetSymbolAddress((void**)&h,    g_h);
    cudaGetSymbolAddress((void**)&qkv,  g_qkv);
    cudaGetSymbolAddress((void**)&att,  g_att);
    cudaGetSymbolAddress((void**)&ff,   g_ff);
    cudaGetSymbolAddress((void**)&bqkv, g_bqkv);
    cudaGetSymbolAddress((void**)&wqkv, g_wqkv);
    cudaGetSymbolAddress((void**)&wo,   g_wo);
    cudaGetSymbolAddress((void**)&w1,   g_w1);
    cudaGetSymbolAddress((void**)&w2,   g_w2);
    cudaGetSymbolAddress((void**)&head, g_head);

    cudaFuncSetAttribute(tc_gemm, cudaFuncAttributeMaxDynamicSharedMemorySize,
                         SMEM_BYTES);

    // launch 0: all weight prep in one kernel
    prep_kernel<<<dim3(32768, 6), 256>>>(Wq, Wk, Wv, Wo, W1, W2, headW,
                                         bq, bk, bv,
                                         wqkv, wo, w1, w2, head, bqkv);
    // launch 1
    embed_kernel<<<NROWS, 256>>>(idx, tok, pos, x);

    dim3 gQKV(QKVD / BN, NROWS / BM);        // (24, 32)
    dim3 gDxD(DD / BN, NROWS / BM);          // (8, 32)
    dim3 gDx4D(FFD / BN, NROWS / BM);        // (32, 32)
    dim3 gAttn(TT / 64, BB * HH);            // (16, 64)
    size_t DxD = (size_t)DD * DD;

    for (int l = 0; l < LL; l++) {
        const __half* wqkv_l = wqkv + (size_t)l * DD * QKVD;
        const __half* wo_l = wo + (size_t)l * DxD;
        const __half* w1_l = w1 + (size_t)l * DD * FFD;
        const __half* w2_l = w2 + (size_t)l * DD * FFD;

        ln_kernel<<<512, 256>>>(x, ln1g + l * DD, ln1b + l * DD, h);
        tc_gemm<<<gQKV, 256, SMEM_BYTES>>>(h, wqkv_l, bqkv + (size_t)l * QKVD,
                                           nullptr, qkv, NROWS, QKVD, DD,
                                           GF_BIAS | GF_OUTHALF);
        fa_kernel<<<gAttn, 128>>>(qkv, att);
        tc_gemm<<<gDxD, 256, SMEM_BYTES>>>(att, wo_l, bo + l * DD, x, x,
                                           NROWS, DD, DD, GF_BIAS | GF_RESID);
        ln_kernel<<<512, 256>>>(x, ln2g + l * DD, ln2b + l * DD, h);
        tc_gemm<<<gDx4D, 256, SMEM_BYTES>>>(h, w1_l, b1 + (size_t)l * FFD,
                                            nullptr, ff, NROWS, FFD, DD,
                                            GF_BIAS | GF_GELU | GF_OUTHALF);
        tc_gemm<<<gDxD, 256, SMEM_BYTES>>>(ff, w2_l, b2 + l * DD, x, x,
                                           NROWS, DD, FFD, GF_BIAS | GF_RESID);
    }

    ln_kernel<<<512, 256>>>(x, lnfg, lnfb, h);
    dim3 gHead(VV / BN, NROWS / BM);         // (250, 32)
    tc_gemm<<<gHead, 256, SMEM_BYTES>>>(h, head, nullptr, nullptr, out,
                                        NROWS, VV, DD, 0);
}

// round 8
// speedup vs baseline: 7.3067x; 1.0769x over previous
#include <cuda_runtime.h>
#include <cuda_fp16.h>
#include <math.h>
#include <stdint.h>

// Problem constants
#define BB 4
#define TT 1024
#define VV 32000
#define DD 1024
#define LL 8
#define HH 16
#define NROWS 4096
#define FFD 4096
#define QKVD 3072

// ---------------- scratch (device globals: allocation-free rule) ----------
__device__ float  g_x[NROWS * DD];                 // residual stream (fp32)
__device__ __half g_h[NROWS * DD];
__device__ __half g_qkv[(size_t)NROWS * QKVD];     // fused q|k|v
__device__ __half g_att[NROWS * DD];
__device__ __half g_ff[NROWS * FFD];
__device__ __half g_wqkv[(size_t)LL * DD * QKVD];  // [K=1024][N=3072] per layer
__device__ float  g_bqkv[LL * QKVD];
__device__ __half g_wo[LL * DD * DD];              // [K][N] row-major fp16
__device__ __half g_w1[(size_t)LL * DD * FFD];
__device__ __half g_w2[(size_t)LL * FFD * DD];
__device__ __half g_head[(size_t)DD * VV];

// ---------------- PTX helpers ---------------------------------------------
__device__ __forceinline__ uint32_t smem_u32(const void* p) {
    uint32_t a;
    asm("{ .reg .u64 t; cvta.to.shared.u64 t, %1; cvt.u32.u64 %0, t; }"
        : "=r"(a) : "l"(p));
    return a;
}
__device__ __forceinline__ void cp16(uint32_t s, const void* g) {
    asm volatile("cp.async.cg.shared.global [%0], [%1], 16;" :: "r"(s), "l"(g));
}
#define CP_COMMIT() asm volatile("cp.async.commit_group;" ::: "memory")
#define CP_WAIT(n) asm volatile("cp.async.wait_group %0;" :: "n"(n) : "memory")

__device__ __forceinline__ void mma_f16(float* c, const uint32_t* a,
                                        const uint32_t* b) {
    asm volatile(
        "mma.sync.aligned.m16n8k16.row.col.f32.f16.f16.f32 "
        "{%0,%1,%2,%3}, {%4,%5,%6,%7}, {%8,%9}, {%0,%1,%2,%3};"
        : "+f"(c[0]), "+f"(c[1]), "+f"(c[2]), "+f"(c[3])
        : "r"(a[0]), "r"(a[1]), "r"(a[2]), "r"(a[3]), "r"(b[0]), "r"(b[1]));
}
__device__ __forceinline__ void ldsm4(uint32_t* r, uint32_t addr) {
    asm volatile("ldmatrix.sync.aligned.m8n8.x4.shared.b16 {%0,%1,%2,%3}, [%4];"
        : "=r"(r[0]), "=r"(r[1]), "=r"(r[2]), "=r"(r[3]) : "r"(addr));
}
__device__ __forceinline__ void ldsm4t(uint32_t* r, uint32_t addr) {
    asm volatile("ldmatrix.sync.aligned.m8n8.x4.trans.shared.b16 {%0,%1,%2,%3}, [%4];"
        : "=r"(r[0]), "=r"(r[1]), "=r"(r[2]), "=r"(r[3]) : "r"(addr));
}
__device__ __forceinline__ void st_half4(__half* p, float4 v) {
    __half2 a = __floats2half2_rn(v.x, v.y);
    __half2 b = __floats2half2_rn(v.z, v.w);
    uint2 u;
    u.x = *(uint32_t*)&a; u.y = *(uint32_t*)&b;
    *(uint2*)p = u;
}

// ---------------- fused weight prep (cast + qkv/bias merge) ----------------
__global__ void prep_kernel(const float* __restrict__ Wq, const float* __restrict__ Wk,
                            const float* __restrict__ Wv, const float* __restrict__ Wo,
                            const float* __restrict__ W1, const float* __restrict__ W2,
                            const float* __restrict__ Hd,
                            const float* __restrict__ bq, const float* __restrict__ bk,
                            const float* __restrict__ bv,
                            __half* __restrict__ wqkv, __half* __restrict__ wo,
                            __half* __restrict__ w1, __half* __restrict__ w2,
                            __half* __restrict__ hd, float* __restrict__ bqkv)
{
    size_t base = ((size_t)blockIdx.x * 256 + threadIdx.x) * 4;
    switch (blockIdx.y) {
    case 0: {   // merged qkv weight: [l][k][n<3072]
        if (base >= (size_t)LL * DD * QKVD) return;
        size_t n = base % QKVD, lk = base / QKVD;
        const float* s = (n < DD) ? Wq : (n < 2 * DD) ? Wk : Wv;
        size_t nn = n & (DD - 1);
        st_half4(wqkv + base, *(const float4*)(s + lk * DD + nn));
        break; }
    case 1: {
        if (base >= (size_t)LL * DD * DD) return;
        st_half4(wo + base, *(const float4*)(Wo + base));
        break; }
    case 2: {
        if (base >= (size_t)LL * DD * FFD) return;
        st_half4(w1 + base, *(const float4*)(W1 + base));
        break; }
    case 3: {
        if (base >= (size_t)LL * FFD * DD) return;
        st_half4(w2 + base, *(const float4*)(W2 + base));
        break; }
    case 4: {
        if (base >= (size_t)DD * VV) return;
        st_half4(hd + base, *(const float4*)(Hd + base));
        break; }
    default: {  // merged qkv bias (fp32)
        if (base >= (size_t)LL * QKVD) return;
        size_t n = base % QKVD, l = base / QKVD;
        const float* s = (n < DD) ? bq : (n < 2 * DD) ? bk : bv;
        *(float4*)(bqkv + base) = *(const float4*)(s + l * DD + (n & (DD - 1)));
        break; }
    }
}

// ---------------- embedding ------------------------------------------------
__global__ void embed_kernel(const int* __restrict__ idx,
                             const float* __restrict__ tok,
                             const float* __restrict__ pos,
                             float* __restrict__ x)
{
    int row = blockIdx.x;
    int t = row % TT;
    int id = idx[row];
    int tid = threadIdx.x;
    const float4* tp = (const float4*)(tok + (size_t)id * DD);
    const float4* pp = (const float4*)(pos + (size_t)t * DD);
    float4 a = tp[tid], b = pp[tid];
    ((float4*)(x + (size_t)row * DD))[tid] =
        make_float4(a.x + b.x, a.y + b.y, a.z + b.z, a.w + b.w);
}

// ---------------- layernorm: warp-per-row, fp32 in / fp16 out --------------
__global__ void ln_kernel(const float* __restrict__ x,
                          const float* __restrict__ g,
                          const float* __restrict__ b,
                          __half* __restrict__ y)
{
    int lane = threadIdx.x & 31, warp = threadIdx.x >> 5;
    int row = blockIdx.x * 8 + warp;
    const float4* xr = (const float4*)(x + (size_t)row * DD);
    float4 v[8];
    float s = 0.f, sq = 0.f;
#pragma unroll
    for (int i = 0; i < 8; i++) {
        v[i] = xr[i * 32 + lane];
        s  += v[i].x + v[i].y + v[i].z + v[i].w;
        sq += v[i].x * v[i].x + v[i].y * v[i].y + v[i].z * v[i].z + v[i].w * v[i].w;
    }
#pragma unroll
    for (int o = 16; o > 0; o >>= 1) {
        s  += __shfl_xor_sync(0xffffffffu, s, o);
        sq += __shfl_xor_sync(0xffffffffu, sq, o);
    }
    float mean = s * (1.f / DD);
    float var  = sq * (1.f / DD) - mean * mean;
    float inv  = rsqrtf(var + 1e-5f);
    const float4* gr = (const float4*)g;
    const float4* br = (const float4*)b;
    __half* yrow = y + (size_t)row * DD;
#pragma unroll
    for (int i = 0; i < 8; i++) {
        float4 gv = gr[i * 32 + lane], bv = br[i * 32 + lane];
        float4 o;
        o.x = (v[i].x - mean) * inv * gv.x + bv.x;
        o.y = (v[i].y - mean) * inv * gv.y + bv.y;
        o.z = (v[i].z - mean) * inv * gv.z + bv.z;
        o.w = (v[i].w - mean) * inv * gv.w + bv.w;
        st_half4(yrow + (i * 32 + lane) * 4, o);
    }
}

// ---------------- fp16 mma.sync GEMM: 4 warps, warp tile 64x64 -------------
// C[M,N] = A[M,K] @ B[K,N]. CTA 128x128, warp tile 64x64, 2 CTAs/SM.
#define GF_BIAS    1
#define GF_GELU    2
#define GF_RESID   4
#define GF_OUTHALF 8
#define BM 128
#define BN 128
#define BK 32
#define PADH 40                        // A row pad (halves)
#define PADB 136                       // B row pad (halves)
#define A_STGH (BM * PADH)             // 5120
#define B_STGH (BK * PADB)             // 4352
#define STGH   (A_STGH + B_STGH)       // 9472 halves = 18944 B
#define NST 5
#define SMEM_BYTES (NST * STGH * 2)    // 94720 B

__global__ void __launch_bounds__(128, 2)
tc_gemm(const __half* __restrict__ A, const __half* __restrict__ B,
        const float* __restrict__ bias, const float* __restrict__ resid,
        void* __restrict__ Cout, int M, int N, int K, int flags)
{
    extern __shared__ __half smh[];
    int tid = threadIdx.x;
    int warp = tid >> 5, lane = tid & 31;
    int grp = lane >> 2, tig = lane & 3;
    int row0 = blockIdx.y * BM, col0 = blockIdx.x * BN;
    int NIT = K / BK;
    int m0 = (warp & 1) * 64, n0 = (warp >> 1) * 64;

    uint32_t smb = smem_u32(smh);

    auto load_tile = [&](int slot, int kt) {
        uint32_t ab = smb + slot * (STGH * 2);
        uint32_t bb = ab + A_STGH * 2;
        int k0 = kt * BK;
#pragma unroll
        for (int i = 0; i < 4; i++) {          // A: 512 chunks of 8 halves
            int lin = i * 128 + tid;
            int m = lin >> 2, j = lin & 3;
            cp16(ab + (m * PADH + j * 8) * 2,
                 A + (size_t)(row0 + m) * K + k0 + j * 8);
        }
#pragma unroll
        for (int i = 0; i < 4; i++) {          // B: 512 chunks ([BK][BN])
            int lin = i * 128 + tid;
            int kr = lin >> 4, nc = lin & 15;
            cp16(bb + (kr * PADB + nc * 8) * 2,
                 B + (size_t)(k0 + kr) * N + col0 + nc * 8);
        }
    };

    float acc[4][8][4];
#pragma unroll
    for (int mt = 0; mt < 4; mt++)
#pragma unroll
        for (int nt = 0; nt < 8; nt++)
#pragma unroll
            for (int r = 0; r < 4; r++) acc[mt][nt][r] = 0.f;

    uint32_t a_off = (uint32_t)(((m0 + (lane & 7) + 8 * ((lane >> 3) & 1)) * PADH
                     + 8 * ((lane >> 4) & 1)) * 2);
    // B trans: row (lane&7)+8*bit3, col n0 + 8*bit4 (+nt2*16)
    uint32_t b_off = (uint32_t)(A_STGH * 2 +
                     (((lane & 7) + 8 * ((lane >> 3) & 1)) * PADB
                     + n0 + 8 * ((lane >> 4) & 1)) * 2);

    load_tile(0, 0); CP_COMMIT();
    load_tile(1, 1); CP_COMMIT();
    load_tile(2, 2); CP_COMMIT();
    load_tile(3, 3); CP_COMMIT();

    int slot = 0;
    for (int it = 0; it < NIT; it++) {
        int rem = NIT - 1 - it;
        if (rem >= 3)      CP_WAIT(3);
        else if (rem == 2) CP_WAIT(2);
        else if (rem == 1) CP_WAIT(1);
        else               CP_WAIT(0);
        __syncthreads();
        if (it + 4 < NIT) {
            int ns = slot + 4; if (ns >= NST) ns -= NST;
            load_tile(ns, it + 4); CP_COMMIT();
        }

        uint32_t stage = smb + slot * (STGH * 2);
#pragma unroll
        for (int kk = 0; kk < 2; kk++) {
            uint32_t af[4][4], bq[4][4];
#pragma unroll
            for (int mt = 0; mt < 4; mt++)
                ldsm4(af[mt], stage + a_off + (mt * 16 * PADH + kk * 16) * 2);
#pragma unroll
            for (int nt2 = 0; nt2 < 4; nt2++)
                ldsm4t(bq[nt2], stage + b_off + (kk * 16 * PADB + nt2 * 16) * 2);
#pragma unroll
            for (int mt = 0; mt < 4; mt++)
#pragma unroll
                for (int nt = 0; nt < 8; nt++)
                    mma_f16(acc[mt][nt], af[mt], &bq[nt >> 1][(nt & 1) * 2]);
        }
        if (++slot >= NST) slot = 0;
    }

    // ---- epilogue ---------------------------------------------------------
#pragma unroll
    for (int mt = 0; mt < 4; mt++) {
#pragma unroll
        for (int half = 0; half < 2; half++) {
            int r = row0 + m0 + mt * 16 + grp + half * 8;
            const float* rrow = (flags & GF_RESID) ? resid + (size_t)r * N : nullptr;
#pragma unroll
            for (int nt = 0; nt < 8; nt++) {
                int c = col0 + n0 + nt * 8 + 2 * tig;
                float v0 = acc[mt][nt][half * 2 + 0];
                float v1 = acc[mt][nt][half * 2 + 1];
                if (flags & GF_BIAS) { v0 += bias[c]; v1 += bias[c + 1]; }
                if (flags & GF_GELU) {
                    v0 = 0.5f * v0 * (1.f + erff(v0 * 0.70710678118654752f));
                    v1 = 0.5f * v1 * (1.f + erff(v1 * 0.70710678118654752f));
                }
                if (flags & GF_RESID) {
                    float2 rv = *(const float2*)(rrow + c);
                    v0 += rv.x; v1 += rv.y;
                }
                if (flags & GF_OUTHALF) {
                    *(__half2*)((__half*)Cout + (size_t)r * N + c) =
                        __floats2half2_rn(v0, v1);
                } else {
                    *(float2*)((float*)Cout + (size_t)r * N + c) =
                        make_float2(v0, v1);
                }
            }
        }
    }
}

// ---------------- tensor-core flash attention (fused qkv input) ------------
__global__ void __launch_bounds__(128, 1) fa_kernel(
    const __half* __restrict__ QKV, __half* __restrict__ O)
{
    __shared__ __half Qs[64][72];
    __shared__ __half Ks[64][72];
    __shared__ __half Vt[64][72];

    int tid = threadIdx.x;
    int warp = tid >> 5, lane = tid & 31;
    int grp = lane >> 2, tig = lane & 3;
    int bh = blockIdx.y;
    int b = bh >> 4, h = bh & 15;
    int q0 = blockIdx.x * 64;

    size_t bq_ = ((size_t)b * TT) * QKVD + (size_t)h * 64;
    size_t bk_ = bq_ + DD;
    size_t bv_ = bq_ + 2 * DD;
    size_t bo_ = ((size_t)b * TT) * DD + (size_t)h * 64;

    const __half2 sc2 = __floats2half2_rn(0.125f, 0.125f);
    for (int i = tid; i < 64 * 8; i += 128) {
        int row = i >> 3, c8 = (i & 7) * 8;
        uint4 u = *(const uint4*)(QKV + bq_ + (size_t)(q0 + row) * QKVD + c8);
        __half2* hp = (__half2*)&u;
#pragma unroll
        for (int j = 0; j < 4; j++) hp[j] = __hmul2(hp[j], sc2);
        *(uint4*)&Qs[row][c8] = u;
    }
    __syncthreads();

    uint32_t aq[4][4];
    int mrow = warp * 16;
#pragma unroll
    for (int s = 0; s < 4; s++) {
        aq[s][0] = *(const uint32_t*)&Qs[mrow + grp][16 * s + 2 * tig];
        aq[s][1] = *(const uint32_t*)&Qs[mrow + grp + 8][16 * s + 2 * tig];
        aq[s][2] = *(const uint32_t*)&Qs[mrow + grp][16 * s + 2 * tig + 8];
        aq[s][3] = *(const uint32_t*)&Qs[mrow + grp + 8][16 * s + 2 * tig + 8];
    }

    float o[8][4];
#pragma unroll
    for (int d = 0; d < 8; d++)
#pragma unroll
        for (int r = 0; r < 4; r++) o[d][r] = 0.f;
    float m0v = -1e30f, m1v = -1e30f, l0 = 0.f, l1 = 0.f;

    for (int kt0 = 0; kt0 <= q0; kt0 += 64) {
        __syncthreads();
        for (int i = tid; i < 64 * 8; i += 128) {
            int row = i >> 3, c8 = (i & 7) * 8;
            *(uint4*)&Ks[row][c8] =
                *(const uint4*)(QKV + bk_ + (size_t)(kt0 + row) * QKVD + c8);
        }
        for (int i = tid; i < 64 * 32; i += 128) {
            int row = i & 63, cp = i >> 6;
            __half2 v = *(const __half2*)(QKV + bv_ + (size_t)(kt0 + row) * QKVD + cp * 2);
            Vt[cp * 2][row] = __low2half(v);
            Vt[cp * 2 + 1][row] = __high2half(v);
        }
        __syncthreads();

        float sc[8][4];
#pragma unroll
        for (int j = 0; j < 8; j++)
#pragma unroll
            for (int r = 0; r < 4; r++) sc[j][r] = 0.f;
#pragma unroll
        for (int s = 0; s < 4; s++) {
#pragma unroll
            for (int j = 0; j < 8; j++) {
                uint32_t bf[2];
                bf[0] = *(const uint32_t*)&Ks[8 * j + grp][16 * s + 2 * tig];
                bf[1] = *(const uint32_t*)&Ks[8 * j + grp][16 * s + 2 * tig + 8];
                mma_f16(sc[j], aq[s], bf);
            }
        }

        if (kt0 == q0) {
            int lq0 = mrow + grp, lq1 = mrow + grp + 8;
#pragma unroll
            for (int j = 0; j < 8; j++) {
                int lk = 8 * j + 2 * tig;
                if (lk > lq0)     sc[j][0] = -1e30f;
                if (lk + 1 > lq0) sc[j][1] = -1e30f;
                if (lk > lq1)     sc[j][2] = -1e30f;
                if (lk + 1 > lq1) sc[j][3] = -1e30f;
            }
        }

        float mx0 = -1e30f, mx1 = -1e30f;
#pragma unroll
        for (int j = 0; j < 8; j++) {
            mx0 = fmaxf(mx0, fmaxf(sc[j][0], sc[j][1]));
            mx1 = fmaxf(mx1, fmaxf(sc[j][2], sc[j][3]));
        }
        mx0 = fmaxf(mx0, __shfl_xor_sync(0xffffffffu, mx0, 1));
        mx0 = fmaxf(mx0, __shfl_xor_sync(0xffffffffu, mx0, 2));
        mx1 = fmaxf(mx1, __shfl_xor_sync(0xffffffffu, mx1, 1));
        mx1 = fmaxf(mx1, __shfl_xor_sync(0xffffffffu, mx1, 2));

        float mn0 = fmaxf(m0v, mx0), mn1 = fmaxf(m1v, mx1);
        float cr0 = __expf(m0v - mn0), cr1 = __expf(m1v - mn1);
        m0v = mn0; m1v = mn1;

        uint32_t ap[4][4];
        float rs0 = 0.f, rs1 = 0.f;
#pragma unroll
        for (int j = 0; j < 8; j++) {
            float p0 = __expf(sc[j][0] - mn0);
            float p1 = __expf(sc[j][1] - mn0);
            float p2 = __expf(sc[j][2] - mn1);
            float p3 = __expf(sc[j][3] - mn1);
            rs0 += p0 + p1; rs1 += p2 + p3;
            int s = j >> 1, odd = j & 1;
            __half2 h01 = __floats2half2_rn(p0, p1);
            __half2 h23 = __floats2half2_rn(p2, p3);
            ap[s][odd * 2 + 0] = *(uint32_t*)&h01;
            ap[s][odd * 2 + 1] = *(uint32_t*)&h23;
        }
        rs0 += __shfl_xor_sync(0xffffffffu, rs0, 1);
        rs0 += __shfl_xor_sync(0xffffffffu, rs0, 2);
        rs1 += __shfl_xor_sync(0xffffffffu, rs1, 1);
        rs1 += __shfl_xor_sync(0xffffffffu, rs1, 2);
        l0 = l0 * cr0 + rs0;
        l1 = l1 * cr1 + rs1;

#pragma unroll
        for (int d = 0; d < 8; d++) {
            o[d][0] *= cr0; o[d][1] *= cr0;
            o[d][2] *= cr1; o[d][3] *= cr1;
        }

#pragma unroll
        for (int s = 0; s < 4; s++) {
#pragma unroll
            for (int d = 0; d < 8; d++) {
                uint32_t bf[2];
                bf[0] = *(const uint32_t*)&Vt[8 * d + grp][16 * s + 2 * tig];
                bf[1] = *(const uint32_t*)&Vt[8 * d + grp][16 * s + 2 * tig + 8];
                mma_f16(o[d], ap[s], bf);
            }
        }
    }

    float i0 = 1.f / l0, i1 = 1.f / l1;
    int r0 = q0 + mrow + grp, r1 = r0 + 8;
#pragma unroll
    for (int d = 0; d < 8; d++) {
        int c = 8 * d + 2 * tig;
        *(__half2*)(O + bo_ + (size_t)r0 * DD + c) =
            __floats2half2_rn(o[d][0] * i0, o[d][1] * i0);
        *(__half2*)(O + bo_ + (size_t)r1 * DD + c) =
            __floats2half2_rn(o[d][2] * i1, o[d][3] * i1);
    }
}

// ---------------- host orchestration ---------------------------------------
extern "C" void kernel_launch(void* const* d_in, const int* in_sizes, int n_in,
                              void* d_out, int out_size)
{
    const int*   idx    = (const int*)  d_in[0];
    const float* tok    = (const float*)d_in[1];
    const float* pos    = (const float*)d_in[2];
    const float* ln1g   = (const float*)d_in[3];
    const float* ln1b   = (const float*)d_in[4];
    const float* Wq     = (const float*)d_in[5];
    const float* bq     = (const float*)d_in[6];
    const float* Wk     = (const float*)d_in[7];
    const float* bk     = (const float*)d_in[8];
    const float* Wv     = (const float*)d_in[9];
    const float* bv     = (const float*)d_in[10];
    const float* Wo     = (const float*)d_in[11];
    const float* bo     = (const float*)d_in[12];
    const float* ln2g   = (const float*)d_in[13];
    const float* ln2b   = (const float*)d_in[14];
    const float* W1     = (const float*)d_in[15];
    const float* b1     = (const float*)d_in[16];
    const float* W2     = (const float*)d_in[17];
    const float* b2     = (const float*)d_in[18];
    const float* lnfg   = (const float*)d_in[19];
    const float* lnfb   = (const float*)d_in[20];
    const float* headW  = (const float*)d_in[21];
    float* out = (float*)d_out;

    float *x, *bqkv;
    __half *h, *qkv, *att, *ff;
    __half *wqkv, *wo, *w1, *w2, *head;
    cudaGetSymbolAddress((void**)&x,    g_x);
    cudaGetSymbolAddress((void**)&h,    g_h);
    cudaGetSymbolAddress((void**)&qkv,  g_qkv);
    cudaGetSymbolAddress((void**)&att,  g_att);
    cudaGetSymbolAddress((void**)&ff,   g_ff);
    cudaGetSymbolAddress((void**)&bqkv, g_bqkv);
    cudaGetSymbolAddress((void**)&wqkv, g_wqkv);
    cudaGetSymbolAddress((void**)&wo,   g_wo);
    cudaGetSymbolAddress((void**)&w1,   g_w1);
    cudaGetSymbolAddress((void**)&w2,   g_w2);
    cudaGetSymbolAddress((void**)&head, g_head);

    cudaFuncSetAttribute(tc_gemm, cudaFuncAttributeMaxDynamicSharedMemorySize,
                         SMEM_BYTES);

    prep_kernel<<<dim3(32768, 6), 256>>>(Wq, Wk, Wv, Wo, W1, W2, headW,
                                         bq, bk, bv,
                                         wqkv, wo, w1, w2, head, bqkv);
    embed_kernel<<<NROWS, 256>>>(idx, tok, pos, x);

    dim3 gQKV(QKVD / BN, NROWS / BM);        // (24, 32)
    dim3 gDxD(DD / BN, NROWS / BM);          // (8, 32)
    dim3 gDx4D(FFD / BN, NROWS / BM);        // (32, 32)
    dim3 gAttn(TT / 64, BB * HH);            // (16, 64)
    size_t DxD = (size_t)DD * DD;

    for (int l = 0; l < LL; l++) {
        const __half* wqkv_l = wqkv + (size_t)l * DD * QKVD;
        const __half* wo_l = wo + (size_t)l * DxD;
        const __half* w1_l = w1 + (size_t)l * DD * FFD;
        const __half* w2_l = w2 + (size_t)l * DD * FFD;

        ln_kernel<<<512, 256>>>(x, ln1g + l * DD, ln1b + l * DD, h);
        tc_gemm<<<gQKV, 128, SMEM_BYTES>>>(h, wqkv_l, bqkv + (size_t)l * QKVD,
                                           nullptr, qkv, NROWS, QKVD, DD,
                                           GF_BIAS | GF_OUTHALF);
        fa_kernel<<<gAttn, 128>>>(qkv, att);
        tc_gemm<<<gDxD, 128, SMEM_BYTES>>>(att, wo_l, bo + l * DD, x, x,
                                           NROWS, DD, DD, GF_BIAS | GF_RESID);
        ln_kernel<<<512, 256>>>(x, ln2g + l * DD, ln2b + l * DD, h);
        tc_gemm<<<gDx4D, 128, SMEM_BYTES>>>(h, w1_l, b1 + (size_t)l * FFD,
                                            nullptr, ff, NROWS, FFD, DD,
                                            GF_BIAS | GF_GELU | GF_OUTHALF);
        tc_gemm<<<gDxD, 128, SMEM_BYTES>>>(ff, w2_l, b2 + l * DD, x, x,
                                           NROWS, DD, FFD, GF_BIAS | GF_RESID);
    }

    ln_kernel<<<512, 256>>>(x, lnfg, lnfb, h);
    dim3 gHead(VV / BN, NROWS / BM);         // (250, 32)
    tc_gemm<<<gHead, 128, SMEM_BYTES>>>(h, head, nullptr, nullptr, out,
                                        NROWS, VV, DD, 0);
}